// round 5
// baseline (speedup 1.0000x reference)
#include <cuda_runtime.h>
#include <math.h>

#define IN_DIM 256
#define HID    128
#define MAXN   100000

// ---- scratch (static device globals; no allocations allowed) ----
__device__ __align__(16) float g_y[(size_t)MAXN * HID];     // y = x @ lin_l_w.T
__device__ __align__(16) float g_acc[(size_t)MAXN * HID];   // scatter-sum of y over edges
__device__ __align__(16) float g_deg[MAXN];
__device__ __align__(16) float g_v[IN_DIM];                 // v = rp_w.T @ sh_w
__device__ float g_c0;                                      // rp_b . sh_w + sh_b
__device__ int   g_is64;                                    // edge_index dtype flag

// ============================================================================
// detect: int64 edge ids < 2^31 have all-zero odd 32-bit words.
// int32 ids in [0,1e5) make that pattern astronomically unlikely over 64 samples.
// ============================================================================
__global__ void detect_kernel(const unsigned* __restrict__ ei32) {
    int any = 0;
    for (int i = threadIdx.x; i < 64; i += 32)
        if (ei32[2 * i + 1] != 0u) any = 1;
    any = __any_sync(0xffffffffu, any);
    if (threadIdx.x == 0) g_is64 = !any;
}

// ============================================================================
// prep: v[k] = sum_h rp_w[h][k] * sh_w[h];  c0 = rp_b . sh_w + sh_b
// ============================================================================
__global__ void prep_kernel(const float* __restrict__ rp_w,
                            const float* __restrict__ rp_b,
                            const float* __restrict__ sh_w,
                            const float* __restrict__ sh_b) {
    int k = threadIdx.x;  // 256 threads
    float s = 0.f;
    for (int h = 0; h < HID; ++h) s += rp_w[h * IN_DIM + k] * sh_w[h];
    g_v[k] = s;
    if (k == 0) {
        float c = sh_b[0];
        for (int h = 0; h < HID; ++h) c += rp_b[h] * sh_w[h];
        g_c0 = c;
    }
}

// ============================================================================
// base: out[i] = a*rr[i] + (1-a)*(x[i].v + c0)
// one warp per node
// ============================================================================
__global__ void base_kernel(const float* __restrict__ x,
                            const float* __restrict__ rr,
                            const float* __restrict__ alpha,
                            float* __restrict__ out, int N) {
    int node = blockIdx.x * 8 + (threadIdx.x >> 5);
    int lane = threadIdx.x & 31;
    if (node >= N) return;
    const float4* xp = reinterpret_cast<const float4*>(x + (size_t)node * IN_DIM);
    const float4* vp = reinterpret_cast<const float4*>(g_v);
    float4 a1 = xp[lane],      b1 = vp[lane];
    float4 a2 = xp[lane + 32], b2 = vp[lane + 32];
    float s = a1.x*b1.x + a1.y*b1.y + a1.z*b1.z + a1.w*b1.w
            + a2.x*b2.x + a2.y*b2.y + a2.z*b2.z + a2.w*b2.w;
    #pragma unroll
    for (int o = 16; o; o >>= 1) s += __shfl_xor_sync(0xffffffffu, s, o);
    if (lane == 0) {
        float av = 1.f / (1.f + expf(-alpha[0]));
        out[node] = av * rr[node] + (1.f - av) * (s + g_c0);
    }
}

// ============================================================================
// zero acc + deg
// ============================================================================
__global__ void zero_kernel(int N) {
    int i = blockIdx.x * blockDim.x + threadIdx.x;
    float4 z = make_float4(0.f, 0.f, 0.f, 0.f);
    if (i < N * (HID / 4)) reinterpret_cast<float4*>(g_acc)[i] = z;
    if (i < (N + 3) / 4)   reinterpret_cast<float4*>(g_deg)[i] = z;
}

// ============================================================================
// edge scatter: warp per edge; acc[dst] += y[src]; deg[dst] += 1
// dtype-agnostic via g_is64; indices clamped so OOB is structurally impossible
// ============================================================================
__global__ void edge_kernel(const int* __restrict__ ei, int E, int N) {
    int w = blockIdx.x * 8 + (threadIdx.x >> 5);
    int lane = threadIdx.x & 31;
    if (w >= E) return;
    int src, dst;
    if (g_is64) {
        const long long* e64 = reinterpret_cast<const long long*>(ei);
        src = (int)e64[w];
        dst = (int)e64[(size_t)E + w];
    } else {
        src = ei[w];
        dst = ei[(size_t)E + w];
    }
    src = min(max(src, 0), N - 1);
    dst = min(max(dst, 0), N - 1);
    float4 v = reinterpret_cast<const float4*>(g_y + (size_t)src * HID)[lane];
    float* ap = g_acc + (size_t)dst * HID + lane * 4;
    atomicAdd(ap + 0, v.x);
    atomicAdd(ap + 1, v.y);
    atomicAdd(ap + 2, v.z);
    atomicAdd(ap + 3, v.w);
    if (lane == 0) atomicAdd(g_deg + dst, 1.0f);
}

// ============================================================================
// GEMM: C[128 tile][128] = x_tile[128][256] @ W[128][256]^T  (fp32, f32x2 packed)
// mode 0: write g_y.    mode 1: fused epilogue -> out += (1-a)*sum_n relu(z)*sh_w
//   z = acc/deg + lin_l_b + r
// block: 256 threads; thread tile 8(m, stride16) x 8(n, stride16); BK=16
// ============================================================================
__global__ __launch_bounds__(256, 1)
void gemm_kernel(const float* __restrict__ x, const float* __restrict__ w,
                 int N, int mode,
                 const float* __restrict__ lin_l_b,
                 const float* __restrict__ sh_w,
                 const float* __restrict__ alpha,
                 float* __restrict__ out) {
    __shared__ float2 sX[2][8][HID];   // [buf][k-pair][m]
    __shared__ float2 sW[2][8][HID];   // [buf][k-pair][n]
    __shared__ float  sB[HID], sS[HID], sInv[HID], sRow[HID];

    const int tid = threadIdx.x;
    const int tx = tid & 15;        // n-group
    const int ty = tid >> 4;        // m-group
    const int m0 = blockIdx.x * 128;

    if (mode == 1 && tid < HID) { sB[tid] = lin_l_b[tid]; sS[tid] = sh_w[tid]; }

    // cooperative stage-load mapping: thread -> (row lr, k-offset lc)
    const int lr = tid >> 1;              // 0..127 (m for x, n for W)
    const int lc = (tid & 1) * 8;         // 0 or 8
    const int lc2 = lc >> 1;              // 0 or 4
    const int xr = min(m0 + lr, N - 1);
    const float* xrow = x + (size_t)xr * IN_DIM + lc;
    const float* wrow = w + (size_t)lr * IN_DIM + lc;

    unsigned long long acc[8][8];
    #pragma unroll
    for (int i = 0; i < 8; ++i)
        #pragma unroll
        for (int j = 0; j < 8; ++j) acc[i][j] = 0ull;

    float4 px0 = *reinterpret_cast<const float4*>(xrow);
    float4 px1 = *reinterpret_cast<const float4*>(xrow + 4);
    float4 pw0 = *reinterpret_cast<const float4*>(wrow);
    float4 pw1 = *reinterpret_cast<const float4*>(wrow + 4);

    int buf = 0;
    for (int s = 0; s < 16; ++s) {
        // store current stage regs -> smem[buf]
        sX[buf][lc2 + 0][lr] = make_float2(px0.x, px0.y);
        sX[buf][lc2 + 1][lr] = make_float2(px0.z, px0.w);
        sX[buf][lc2 + 2][lr] = make_float2(px1.x, px1.y);
        sX[buf][lc2 + 3][lr] = make_float2(px1.z, px1.w);
        sW[buf][lc2 + 0][lr] = make_float2(pw0.x, pw0.y);
        sW[buf][lc2 + 1][lr] = make_float2(pw0.z, pw0.w);
        sW[buf][lc2 + 2][lr] = make_float2(pw1.x, pw1.y);
        sW[buf][lc2 + 3][lr] = make_float2(pw1.z, pw1.w);
        __syncthreads();

        if (s < 15) {
            int ko = (s + 1) * 16;
            px0 = *reinterpret_cast<const float4*>(xrow + ko);
            px1 = *reinterpret_cast<const float4*>(xrow + ko + 4);
            pw0 = *reinterpret_cast<const float4*>(wrow + ko);
            pw1 = *reinterpret_cast<const float4*>(wrow + ko + 4);
        }

        #pragma unroll
        for (int k2 = 0; k2 < 8; ++k2) {
            unsigned long long af[8], bf[8];
            #pragma unroll
            for (int i = 0; i < 8; ++i)
                af[i] = *reinterpret_cast<const unsigned long long*>(&sX[buf][k2][ty + 16 * i]);
            #pragma unroll
            for (int j = 0; j < 8; ++j)
                bf[j] = *reinterpret_cast<const unsigned long long*>(&sW[buf][k2][tx + 16 * j]);
            #pragma unroll
            for (int i = 0; i < 8; ++i)
                #pragma unroll
                for (int j = 0; j < 8; ++j)
                    asm("fma.rn.f32x2 %0, %1, %2, %0;"
                        : "+l"(acc[i][j]) : "l"(af[i]), "l"(bf[j]));
        }
        buf ^= 1;
    }

    if (mode == 0) {
        // write y
        #pragma unroll
        for (int i = 0; i < 8; ++i) {
            int node = m0 + ty + 16 * i;
            if (node < N) {
                #pragma unroll
                for (int j = 0; j < 8; ++j) {
                    unsigned long long p = acc[i][j];
                    float lo = __uint_as_float((unsigned)(p & 0xffffffffull));
                    float hi = __uint_as_float((unsigned)(p >> 32));
                    g_y[(size_t)node * HID + tx + 16 * j] = lo + hi;
                }
            }
        }
    } else {
        __syncthreads();
        if (tid < HID) {
            int node = m0 + tid;
            sInv[tid] = (node < N) ? (1.f / fmaxf(g_deg[node], 1.f)) : 0.f;
            sRow[tid] = 0.f;
        }
        __syncthreads();
        #pragma unroll
        for (int i = 0; i < 8; ++i) {
            int m = ty + 16 * i;
            int node = m0 + m;
            if (node < N) {
                float inv = sInv[m];
                float part = 0.f;
                #pragma unroll
                for (int j = 0; j < 8; ++j) {
                    int n = tx + 16 * j;
                    unsigned long long p = acc[i][j];
                    float lo = __uint_as_float((unsigned)(p & 0xffffffffull));
                    float hi = __uint_as_float((unsigned)(p >> 32));
                    float r = lo + hi;
                    float z = g_acc[(size_t)node * HID + n] * inv + sB[n] + r;
                    part += fmaxf(z, 0.f) * sS[n];
                }
                atomicAdd(&sRow[m], part);
            }
        }
        __syncthreads();
        if (tid < HID) {
            int node = m0 + tid;
            if (node < N) {
                float av = 1.f / (1.f + expf(-alpha[0]));
                out[node] += (1.f - av) * sRow[tid];
            }
        }
    }
}

// ============================================================================
extern "C" void kernel_launch(void* const* d_in, const int* in_sizes, int n_in,
                              void* d_out, int out_size) {
    const float* x        = (const float*)d_in[0];
    const int*   ei       = (const int*)d_in[1];
    const float* rr       = (const float*)d_in[2];
    const float* lin_l_w  = (const float*)d_in[3];
    const float* lin_l_b  = (const float*)d_in[4];
    const float* lin_r_w  = (const float*)d_in[5];
    const float* rp_w     = (const float*)d_in[6];
    const float* rp_b     = (const float*)d_in[7];
    const float* sh_w     = (const float*)d_in[8];
    const float* sh_b     = (const float*)d_in[9];
    const float* alpha    = (const float*)d_in[10];
    float* out = (float*)d_out;

    int N = in_sizes[2];
    int E = in_sizes[1] / 2;

    detect_kernel<<<1, 32>>>((const unsigned*)ei);
    prep_kernel<<<1, 256>>>(rp_w, rp_b, sh_w, sh_b);
    base_kernel<<<(N + 7) / 8, 256>>>(x, rr, alpha, out, N);
    zero_kernel<<<(N * (HID / 4) + 255) / 256, 256>>>(N);
    gemm_kernel<<<(N + 127) / 128, 256>>>(x, lin_l_w, N, 0,
                                          lin_l_b, sh_w, alpha, out);
    edge_kernel<<<(E + 7) / 8, 256>>>(ei, E, N);
    gemm_kernel<<<(N + 127) / 128, 256>>>(x, lin_r_w, N, 1,
                                          lin_l_b, sh_w, alpha, out);
}

// round 6
// speedup vs baseline: 1.1842x; 1.1842x over previous
#include <cuda_runtime.h>
#include <math.h>

#define IN_DIM 256
#define HID    128
#define MAXN   100000
#define MAXE   600000
#define SCAN_B 1024

// ---- scratch (static device globals; no allocations allowed) ----
__device__ __align__(16) float g_y[(size_t)MAXN * HID];     // y = x @ lin_l_w.T
__device__ __align__(16) float g_acc[(size_t)MAXN * HID];   // gathered neighbor sums
__device__ __align__(16) float g_deg[MAXN];
__device__ __align__(16) float g_v[IN_DIM];                 // v = rp_w.T @ sh_w
__device__ float g_c0;                                      // rp_b . sh_w + sh_b
__device__ int   g_is64;                                    // edge_index dtype flag
// CSR build
__device__ int g_cnt[MAXN];
__device__ int g_rowptr[MAXN + 1];
__device__ int g_cursor[MAXN];
__device__ int g_srclist[MAXE];
__device__ int g_bsum[(MAXN + SCAN_B - 1) / SCAN_B + 1];

// ============================================================================
// detect: int64 edge ids < 2^31 have all-zero odd 32-bit words.
// ============================================================================
__global__ void detect_kernel(const unsigned* __restrict__ ei32) {
    int any = 0;
    for (int i = threadIdx.x; i < 64; i += 32)
        if (ei32[2 * i + 1] != 0u) any = 1;
    any = __any_sync(0xffffffffu, any);
    if (threadIdx.x == 0) g_is64 = !any;
}

__device__ __forceinline__ int load_idx(const int* ei, size_t pos) {
    if (g_is64) return (int)reinterpret_cast<const long long*>(ei)[pos];
    return ei[pos];
}

// ============================================================================
// prep: v[k] = sum_h rp_w[h][k] * sh_w[h];  c0 = rp_b . sh_w + sh_b
// ============================================================================
__global__ void prep_kernel(const float* __restrict__ rp_w,
                            const float* __restrict__ rp_b,
                            const float* __restrict__ sh_w,
                            const float* __restrict__ sh_b) {
    int k = threadIdx.x;  // 256 threads
    float s = 0.f;
    for (int h = 0; h < HID; ++h) s += rp_w[h * IN_DIM + k] * sh_w[h];
    g_v[k] = s;
    if (k == 0) {
        float c = sh_b[0];
        for (int h = 0; h < HID; ++h) c += rp_b[h] * sh_w[h];
        g_c0 = c;
    }
}

// ============================================================================
// base: out[i] = a*rr[i] + (1-a)*(x[i].v + c0);  one warp per node
// ============================================================================
__global__ void base_kernel(const float* __restrict__ x,
                            const float* __restrict__ rr,
                            const float* __restrict__ alpha,
                            float* __restrict__ out, int N) {
    int node = blockIdx.x * 8 + (threadIdx.x >> 5);
    int lane = threadIdx.x & 31;
    if (node >= N) return;
    const float4* xp = reinterpret_cast<const float4*>(x + (size_t)node * IN_DIM);
    const float4* vp = reinterpret_cast<const float4*>(g_v);
    float4 a1 = xp[lane],      b1 = vp[lane];
    float4 a2 = xp[lane + 32], b2 = vp[lane + 32];
    float s = a1.x*b1.x + a1.y*b1.y + a1.z*b1.z + a1.w*b1.w
            + a2.x*b2.x + a2.y*b2.y + a2.z*b2.z + a2.w*b2.w;
    #pragma unroll
    for (int o = 16; o; o >>= 1) s += __shfl_xor_sync(0xffffffffu, s, o);
    if (lane == 0) {
        float av = 1.f / (1.f + expf(-alpha[0]));
        out[node] = av * rr[node] + (1.f - av) * (s + g_c0);
    }
}

// ============================================================================
// CSR build
// ============================================================================
__global__ void zero_cnt_kernel(int N) {
    int i = blockIdx.x * blockDim.x + threadIdx.x;
    if (i < N) g_cnt[i] = 0;
}

__global__ void hist_kernel(const int* __restrict__ ei, int E, int N) {
    int e = blockIdx.x * blockDim.x + threadIdx.x;
    if (e >= E) return;
    int dst = load_idx(ei, (size_t)E + e);
    dst = min(max(dst, 0), N - 1);
    atomicAdd(&g_cnt[dst], 1);
}

// per-block exclusive scan (Hillis-Steele over SCAN_B), block totals to g_bsum
__global__ void scanA_kernel(int N) {
    __shared__ int s[SCAN_B];
    int tid = threadIdx.x;
    int i = blockIdx.x * SCAN_B + tid;
    int v = (i < N) ? g_cnt[i] : 0;
    s[tid] = v;
    __syncthreads();
    for (int off = 1; off < SCAN_B; off <<= 1) {
        int t = (tid >= off) ? s[tid - off] : 0;
        __syncthreads();
        s[tid] += t;
        __syncthreads();
    }
    if (i < N) g_rowptr[i] = s[tid] - v;          // exclusive
    if (tid == SCAN_B - 1) g_bsum[blockIdx.x] = s[tid];
}

// exclusive scan over block sums (single block)
__global__ void scanB_kernel(int nb) {
    __shared__ int s[SCAN_B];
    int tid = threadIdx.x;
    int v = (tid < nb) ? g_bsum[tid] : 0;
    s[tid] = v;
    __syncthreads();
    for (int off = 1; off < SCAN_B; off <<= 1) {
        int t = (tid >= off) ? s[tid - off] : 0;
        __syncthreads();
        s[tid] += t;
        __syncthreads();
    }
    if (tid < nb) g_bsum[tid] = s[tid] - v;       // exclusive
}

__global__ void scanC_kernel(int N, int E) {
    int i = blockIdx.x * blockDim.x + threadIdx.x;
    if (i < N) {
        int r = g_rowptr[i] + g_bsum[i / SCAN_B];
        g_rowptr[i] = r;
        g_cursor[i] = r;
    }
    if (i == 0) g_rowptr[N] = E;
}

__global__ void scatter_kernel(const int* __restrict__ ei, int E, int N) {
    int e = blockIdx.x * blockDim.x + threadIdx.x;
    if (e >= E) return;
    int src = load_idx(ei, e);
    int dst = load_idx(ei, (size_t)E + e);
    src = min(max(src, 0), N - 1);
    dst = min(max(dst, 0), N - 1);
    int pos = atomicAdd(&g_cursor[dst], 1);
    if (pos < MAXE) g_srclist[pos] = src;
}

// ============================================================================
// gather: one warp per dst node; atomic-free row accumulation
// ============================================================================
__global__ void gather_kernel(int N) {
    int node = blockIdx.x * 8 + (threadIdx.x >> 5);
    int lane = threadIdx.x & 31;
    if (node >= N) return;
    int s0 = g_rowptr[node], s1 = g_rowptr[node + 1];
    float4 acc = make_float4(0.f, 0.f, 0.f, 0.f);
    int e = s0;
    // 2-way unrolled for MLP
    for (; e + 1 < s1; e += 2) {
        int sa = g_srclist[e], sb = g_srclist[e + 1];
        float4 va = reinterpret_cast<const float4*>(g_y + (size_t)sa * HID)[lane];
        float4 vb = reinterpret_cast<const float4*>(g_y + (size_t)sb * HID)[lane];
        acc.x += va.x + vb.x; acc.y += va.y + vb.y;
        acc.z += va.z + vb.z; acc.w += va.w + vb.w;
    }
    if (e < s1) {
        int sa = g_srclist[e];
        float4 va = reinterpret_cast<const float4*>(g_y + (size_t)sa * HID)[lane];
        acc.x += va.x; acc.y += va.y; acc.z += va.z; acc.w += va.w;
    }
    reinterpret_cast<float4*>(g_acc + (size_t)node * HID)[lane] = acc;
    if (lane == 0) g_deg[node] = (float)(s1 - s0);
}

// ============================================================================
// GEMM: C[128 tile][128] = x_tile[128][256] @ W[128][256]^T  (fp32, f32x2 packed)
// mode 0: write g_y.    mode 1: fused epilogue -> out += (1-a)*sum_n relu(z)*sh_w
// ============================================================================
__global__ __launch_bounds__(256, 1)
void gemm_kernel(const float* __restrict__ x, const float* __restrict__ w,
                 int N, int mode,
                 const float* __restrict__ lin_l_b,
                 const float* __restrict__ sh_w,
                 const float* __restrict__ alpha,
                 float* __restrict__ out) {
    __shared__ float2 sX[2][8][HID];   // [buf][k-pair][m]
    __shared__ float2 sW[2][8][HID];   // [buf][k-pair][n]
    __shared__ float  sB[HID], sS[HID], sInv[HID], sRow[HID];

    const int tid = threadIdx.x;
    const int tx = tid & 15;        // n-group
    const int ty = tid >> 4;        // m-group
    const int m0 = blockIdx.x * 128;

    if (mode == 1 && tid < HID) { sB[tid] = lin_l_b[tid]; sS[tid] = sh_w[tid]; }

    const int lr = tid >> 1;              // 0..127 (m for x, n for W)
    const int lc = (tid & 1) * 8;         // 0 or 8
    const int lc2 = lc >> 1;              // 0 or 4
    const int xr = min(m0 + lr, N - 1);
    const float* xrow = x + (size_t)xr * IN_DIM + lc;
    const float* wrow = w + (size_t)lr * IN_DIM + lc;

    unsigned long long acc[8][8];
    #pragma unroll
    for (int i = 0; i < 8; ++i)
        #pragma unroll
        for (int j = 0; j < 8; ++j) acc[i][j] = 0ull;

    float4 px0 = *reinterpret_cast<const float4*>(xrow);
    float4 px1 = *reinterpret_cast<const float4*>(xrow + 4);
    float4 pw0 = *reinterpret_cast<const float4*>(wrow);
    float4 pw1 = *reinterpret_cast<const float4*>(wrow + 4);

    int buf = 0;
    for (int s = 0; s < 16; ++s) {
        sX[buf][lc2 + 0][lr] = make_float2(px0.x, px0.y);
        sX[buf][lc2 + 1][lr] = make_float2(px0.z, px0.w);
        sX[buf][lc2 + 2][lr] = make_float2(px1.x, px1.y);
        sX[buf][lc2 + 3][lr] = make_float2(px1.z, px1.w);
        sW[buf][lc2 + 0][lr] = make_float2(pw0.x, pw0.y);
        sW[buf][lc2 + 1][lr] = make_float2(pw0.z, pw0.w);
        sW[buf][lc2 + 2][lr] = make_float2(pw1.x, pw1.y);
        sW[buf][lc2 + 3][lr] = make_float2(pw1.z, pw1.w);
        __syncthreads();

        if (s < 15) {
            int ko = (s + 1) * 16;
            px0 = *reinterpret_cast<const float4*>(xrow + ko);
            px1 = *reinterpret_cast<const float4*>(xrow + ko + 4);
            pw0 = *reinterpret_cast<const float4*>(wrow + ko);
            pw1 = *reinterpret_cast<const float4*>(wrow + ko + 4);
        }

        #pragma unroll
        for (int k2 = 0; k2 < 8; ++k2) {
            unsigned long long af[8], bf[8];
            #pragma unroll
            for (int i = 0; i < 8; ++i)
                af[i] = *reinterpret_cast<const unsigned long long*>(&sX[buf][k2][ty + 16 * i]);
            #pragma unroll
            for (int j = 0; j < 8; ++j)
                bf[j] = *reinterpret_cast<const unsigned long long*>(&sW[buf][k2][tx + 16 * j]);
            #pragma unroll
            for (int i = 0; i < 8; ++i)
                #pragma unroll
                for (int j = 0; j < 8; ++j)
                    asm("fma.rn.f32x2 %0, %1, %2, %0;"
                        : "+l"(acc[i][j]) : "l"(af[i]), "l"(bf[j]));
        }
        buf ^= 1;
    }

    if (mode == 0) {
        #pragma unroll
        for (int i = 0; i < 8; ++i) {
            int node = m0 + ty + 16 * i;
            if (node < N) {
                #pragma unroll
                for (int j = 0; j < 8; ++j) {
                    unsigned long long p = acc[i][j];
                    float lo = __uint_as_float((unsigned)(p & 0xffffffffull));
                    float hi = __uint_as_float((unsigned)(p >> 32));
                    g_y[(size_t)node * HID + tx + 16 * j] = lo + hi;
                }
            }
        }
    } else {
        __syncthreads();
        if (tid < HID) {
            int node = m0 + tid;
            sInv[tid] = (node < N) ? (1.f / fmaxf(g_deg[node], 1.f)) : 0.f;
            sRow[tid] = 0.f;
        }
        __syncthreads();
        #pragma unroll
        for (int i = 0; i < 8; ++i) {
            int m = ty + 16 * i;
            int node = m0 + m;
            if (node < N) {
                float inv = sInv[m];
                float part = 0.f;
                #pragma unroll
                for (int j = 0; j < 8; ++j) {
                    int n = tx + 16 * j;
                    unsigned long long p = acc[i][j];
                    float lo = __uint_as_float((unsigned)(p & 0xffffffffull));
                    float hi = __uint_as_float((unsigned)(p >> 32));
                    float r = lo + hi;
                    float z = g_acc[(size_t)node * HID + n] * inv + sB[n] + r;
                    part += fmaxf(z, 0.f) * sS[n];
                }
                atomicAdd(&sRow[m], part);
            }
        }
        __syncthreads();
        if (tid < HID) {
            int node = m0 + tid;
            if (node < N) {
                float av = 1.f / (1.f + expf(-alpha[0]));
                out[node] += (1.f - av) * sRow[tid];
            }
        }
    }
}

// ============================================================================
extern "C" void kernel_launch(void* const* d_in, const int* in_sizes, int n_in,
                              void* d_out, int out_size) {
    const float* x        = (const float*)d_in[0];
    const int*   ei       = (const int*)d_in[1];
    const float* rr       = (const float*)d_in[2];
    const float* lin_l_w  = (const float*)d_in[3];
    const float* lin_l_b  = (const float*)d_in[4];
    const float* lin_r_w  = (const float*)d_in[5];
    const float* rp_w     = (const float*)d_in[6];
    const float* rp_b     = (const float*)d_in[7];
    const float* sh_w     = (const float*)d_in[8];
    const float* sh_b     = (const float*)d_in[9];
    const float* alpha    = (const float*)d_in[10];
    float* out = (float*)d_out;

    int N = in_sizes[2];
    int E = in_sizes[1] / 2;
    if (E > MAXE) E = MAXE;
    int nblkN = (N + SCAN_B - 1) / SCAN_B;

    detect_kernel<<<1, 32>>>((const unsigned*)ei);
    prep_kernel<<<1, 256>>>(rp_w, rp_b, sh_w, sh_b);
    base_kernel<<<(N + 7) / 8, 256>>>(x, rr, alpha, out, N);
    // CSR build (overlaps conceptually with gemm0 on the same stream order)
    zero_cnt_kernel<<<(N + 255) / 256, 256>>>(N);
    hist_kernel<<<(E + 255) / 256, 256>>>(ei, E, N);
    scanA_kernel<<<nblkN, SCAN_B>>>(N);
    scanB_kernel<<<1, SCAN_B>>>(nblkN);
    scanC_kernel<<<(N + 255) / 256, 256>>>(N, E);
    scatter_kernel<<<(E + 255) / 256, 256>>>(ei, E, N);
    // y = x @ lin_l.T
    gemm_kernel<<<(N + 127) / 128, 256>>>(x, lin_l_w, N, 0,
                                          lin_l_b, sh_w, alpha, out);
    // neighbor mean numerators + degrees
    gather_kernel<<<(N + 7) / 8, 256>>>(N);
    // r = x @ lin_r.T, fused epilogue
    gemm_kernel<<<(N + 127) / 128, 256>>>(x, lin_r_w, N, 1,
                                          lin_l_b, sh_w, alpha, out);
}

// round 9
// speedup vs baseline: 2.2354x; 1.8876x over previous
#include <cuda_runtime.h>
#include <cuda_bf16.h>
#include <math.h>
#include <stdint.h>

#define IN_DIM 256
#define HID    128
#define NTOT   256          // concat output cols: [y(128) | r(128)]
#define MAXN   100000
#define MAXE   600000
#define SCAN_B 1024

// ---- scratch (static device globals; no allocations allowed) ----
__device__ __align__(16) float g_yr[(size_t)MAXN * NTOT];   // [y | r] per node
__device__ __align__(16) float g_v[IN_DIM];                 // rp_w.T @ sh_w
__device__ float g_c0;
__device__ int   g_is64;
__device__ int g_cnt[MAXN];
__device__ int g_rowptr[MAXN + 1];
__device__ int g_cursor[MAXN];
__device__ int g_srclist[MAXE];
__device__ int g_bsum[(MAXN + SCAN_B - 1) / SCAN_B + 1];

// ---------------------------------------------------------------- helpers
__device__ __forceinline__ uint32_t smem_u32(const void* p) {
    uint32_t a;
    asm("{ .reg .u64 t; cvta.to.shared.u64 t, %1; cvt.u32.u64 %0, t; }"
        : "=r"(a) : "l"(p));
    return a;
}
__device__ __forceinline__ void ldsm4(uint32_t* r, uint32_t addr) {
    asm volatile("ldmatrix.sync.aligned.m8n8.x4.shared.b16 {%0,%1,%2,%3}, [%4];"
                 : "=r"(r[0]), "=r"(r[1]), "=r"(r[2]), "=r"(r[3]) : "r"(addr));
}
__device__ __forceinline__ void mma16816(float* c, const uint32_t* a,
                                         const uint32_t* b) {
    asm volatile("mma.sync.aligned.m16n8k16.row.col.f32.bf16.bf16.f32 "
                 "{%0,%1,%2,%3}, {%4,%5,%6,%7}, {%8,%9}, {%0,%1,%2,%3};"
                 : "+f"(c[0]), "+f"(c[1]), "+f"(c[2]), "+f"(c[3])
                 : "r"(a[0]), "r"(a[1]), "r"(a[2]), "r"(a[3]),
                   "r"(b[0]), "r"(b[1]));
}
#define SWZ(o) ((o) ^ (((o) >> 3) & 0x70))

// ---------------------------------------------------------------- misc kernels
__global__ void detect_kernel(const unsigned* __restrict__ ei32) {
    int any = 0;
    for (int i = threadIdx.x; i < 64; i += 32)
        if (ei32[2 * i + 1] != 0u) any = 1;
    any = __any_sync(0xffffffffu, any);
    if (threadIdx.x == 0) g_is64 = !any;
}
__device__ __forceinline__ int load_idx(const int* ei, size_t pos) {
    if (g_is64) return (int)reinterpret_cast<const long long*>(ei)[pos];
    return ei[pos];
}

__global__ void prep_kernel(const float* __restrict__ rp_w,
                            const float* __restrict__ rp_b,
                            const float* __restrict__ sh_w,
                            const float* __restrict__ sh_b) {
    int k = threadIdx.x;
    float s = 0.f;
    for (int h = 0; h < HID; ++h) s += rp_w[h * IN_DIM + k] * sh_w[h];
    g_v[k] = s;
    if (k == 0) {
        float c = sh_b[0];
        for (int h = 0; h < HID; ++h) c += rp_b[h] * sh_w[h];
        g_c0 = c;
    }
}

__global__ void base_kernel(const float* __restrict__ x,
                            const float* __restrict__ rr,
                            const float* __restrict__ alpha,
                            float* __restrict__ out, int N) {
    int node = blockIdx.x * 8 + (threadIdx.x >> 5);
    int lane = threadIdx.x & 31;
    if (node >= N) return;
    const float4* xp = reinterpret_cast<const float4*>(x + (size_t)node * IN_DIM);
    const float4* vp = reinterpret_cast<const float4*>(g_v);
    float4 a1 = xp[lane],      b1 = vp[lane];
    float4 a2 = xp[lane + 32], b2 = vp[lane + 32];
    float s = a1.x*b1.x + a1.y*b1.y + a1.z*b1.z + a1.w*b1.w
            + a2.x*b2.x + a2.y*b2.y + a2.z*b2.z + a2.w*b2.w;
    #pragma unroll
    for (int o = 16; o; o >>= 1) s += __shfl_xor_sync(0xffffffffu, s, o);
    if (lane == 0) {
        float av = 1.f / (1.f + expf(-alpha[0]));
        out[node] = av * rr[node] + (1.f - av) * (s + g_c0);
    }
}

// ---------------------------------------------------------------- CSR build
__global__ void zero_cnt_kernel(int N) {
    int i = blockIdx.x * blockDim.x + threadIdx.x;
    if (i < N) g_cnt[i] = 0;
}
__global__ void hist_kernel(const int* __restrict__ ei, int E, int N) {
    int e = blockIdx.x * blockDim.x + threadIdx.x;
    if (e >= E) return;
    int dst = load_idx(ei, (size_t)E + e);
    dst = min(max(dst, 0), N - 1);
    atomicAdd(&g_cnt[dst], 1);
}
__global__ void scanA_kernel(int N) {
    __shared__ int s[SCAN_B];
    int tid = threadIdx.x;
    int i = blockIdx.x * SCAN_B + tid;
    int v = (i < N) ? g_cnt[i] : 0;
    s[tid] = v;
    __syncthreads();
    for (int off = 1; off < SCAN_B; off <<= 1) {
        int t = (tid >= off) ? s[tid - off] : 0;
        __syncthreads();
        s[tid] += t;
        __syncthreads();
    }
    if (i < N) g_rowptr[i] = s[tid] - v;
    if (tid == SCAN_B - 1) g_bsum[blockIdx.x] = s[tid];
}
__global__ void scanB_kernel(int nb) {
    __shared__ int s[SCAN_B];
    int tid = threadIdx.x;
    int v = (tid < nb) ? g_bsum[tid] : 0;
    s[tid] = v;
    __syncthreads();
    for (int off = 1; off < SCAN_B; off <<= 1) {
        int t = (tid >= off) ? s[tid - off] : 0;
        __syncthreads();
        s[tid] += t;
        __syncthreads();
    }
    if (tid < nb) g_bsum[tid] = s[tid] - v;
}
__global__ void scanC_kernel(int N, int E) {
    int i = blockIdx.x * blockDim.x + threadIdx.x;
    if (i < N) {
        int r = g_rowptr[i] + g_bsum[i / SCAN_B];
        g_rowptr[i] = r;
        g_cursor[i] = r;
    }
    if (i == 0) g_rowptr[N] = E;
}
__global__ void scatter_kernel(const int* __restrict__ ei, int E, int N) {
    int e = blockIdx.x * blockDim.x + threadIdx.x;
    if (e >= E) return;
    int src = load_idx(ei, e);
    int dst = load_idx(ei, (size_t)E + e);
    src = min(max(src, 0), N - 1);
    dst = min(max(dst, 0), N - 1);
    int pos = atomicAdd(&g_cursor[dst], 1);
    if (pos < MAXE) g_srclist[pos] = src;
}

// ---------------------------------------------------------------- HMMA GEMM
// D[128 x 256] = X[128 x 256] @ [lin_l ; lin_r]^T
// bf16 split x3 (XhWh + XhWl + XlWh), fp32 accum via mma.sync.m16n8k16.
// 8 warps (4m x 2n), warp tile 32x128. K chunked at 64; X/W converted to
// bf16 hi/lo into SW128-swizzled smem (Xh 16K | Xl 16K | Wh 32K | Wl 32K).
__global__ __launch_bounds__(256, 1)
void mma_kernel(const float* __restrict__ x, const float* __restrict__ wl,
                const float* __restrict__ wr, int N) {
    extern __shared__ char dsm[];
    uint32_t sb   = smem_u32(dsm);
    uint32_t base = (sb + 127) & ~127u;
    char*    db   = dsm + (base - sb);
    uint32_t sXh = base, sXl = base + 16384, sWh = base + 32768, sWl = base + 65536;
    char *pXh = db, *pXl = db + 16384, *pWh = db + 32768, *pWl = db + 65536;

    int tid = threadIdx.x, wid = tid >> 5, lane = tid & 31;
    int wm = wid & 3, wn = wid >> 2;
    int m0 = blockIdx.x * 128;

    // ldmatrix lane address components
    int aRow = (lane & 7) + ((lane >> 3) & 1) * 8;   // A: row within m16
    int aK   = ((lane >> 4) & 1) * 8;                // A: k half
    int bRow = (lane & 7) + ((lane >> 4) & 1) * 8;   // B: n row within n16
    int bK   = ((lane >> 3) & 1) * 8;                // B: k half

    float acc[2][16][4];
    #pragma unroll
    for (int i = 0; i < 2; ++i)
        #pragma unroll
        for (int j = 0; j < 16; ++j)
            #pragma unroll
            for (int q = 0; q < 4; ++q) acc[i][j][q] = 0.f;

    for (int c = 0; c < 4; ++c) {
        if (c) __syncthreads();   // previous chunk's MMA reads done
        // ---- X chunk: 128 rows x 64 feats -> bf16 hi/lo, SW128
        #pragma unroll
        for (int i = 0; i < 8; ++i) {
            int l = tid + i * 256;            // 0..2047
            int row = l >> 4, qf = l & 15;
            int grow = min(m0 + row, N - 1);
            float4 f = *(const float4*)(x + (size_t)grow * IN_DIM + c * 64 + qf * 4);
            __nv_bfloat16 h0 = __float2bfloat16_rn(f.x), h1 = __float2bfloat16_rn(f.y),
                          h2 = __float2bfloat16_rn(f.z), h3 = __float2bfloat16_rn(f.w);
            __nv_bfloat16 e0 = __float2bfloat16_rn(f.x - __bfloat162float(h0));
            __nv_bfloat16 e1 = __float2bfloat16_rn(f.y - __bfloat162float(h1));
            __nv_bfloat16 e2 = __float2bfloat16_rn(f.z - __bfloat162float(h2));
            __nv_bfloat16 e3 = __float2bfloat16_rn(f.w - __bfloat162float(h3));
            uint32_t off = SWZ((uint32_t)(row * 128 + qf * 8));
            uint2 hv, lv;
            hv.x = ((uint32_t)__bfloat16_as_ushort(h1) << 16) | __bfloat16_as_ushort(h0);
            hv.y = ((uint32_t)__bfloat16_as_ushort(h3) << 16) | __bfloat16_as_ushort(h2);
            lv.x = ((uint32_t)__bfloat16_as_ushort(e1) << 16) | __bfloat16_as_ushort(e0);
            lv.y = ((uint32_t)__bfloat16_as_ushort(e3) << 16) | __bfloat16_as_ushort(e2);
            *(uint2*)(pXh + off) = hv;
            *(uint2*)(pXl + off) = lv;
        }
        // ---- W chunk: 256 rows (lin_l then lin_r) x 64 feats
        #pragma unroll
        for (int i = 0; i < 16; ++i) {
            int l = tid + i * 256;            // 0..4095
            int row = l >> 4, qf = l & 15;
            const float* srcp = (row < HID) ? (wl + (size_t)row * IN_DIM)
                                            : (wr + (size_t)(row - HID) * IN_DIM);
            float4 f = *(const float4*)(srcp + c * 64 + qf * 4);
            __nv_bfloat16 h0 = __float2bfloat16_rn(f.x), h1 = __float2bfloat16_rn(f.y),
                          h2 = __float2bfloat16_rn(f.z), h3 = __float2bfloat16_rn(f.w);
            __nv_bfloat16 e0 = __float2bfloat16_rn(f.x - __bfloat162float(h0));
            __nv_bfloat16 e1 = __float2bfloat16_rn(f.y - __bfloat162float(h1));
            __nv_bfloat16 e2 = __float2bfloat16_rn(f.z - __bfloat162float(h2));
            __nv_bfloat16 e3 = __float2bfloat16_rn(f.w - __bfloat162float(h3));
            uint32_t off = SWZ((uint32_t)(row * 128 + qf * 8));
            uint2 hv, lv;
            hv.x = ((uint32_t)__bfloat16_as_ushort(h1) << 16) | __bfloat16_as_ushort(h0);
            hv.y = ((uint32_t)__bfloat16_as_ushort(h3) << 16) | __bfloat16_as_ushort(h2);
            lv.x = ((uint32_t)__bfloat16_as_ushort(e1) << 16) | __bfloat16_as_ushort(e0);
            lv.y = ((uint32_t)__bfloat16_as_ushort(e3) << 16) | __bfloat16_as_ushort(e2);
            *(uint2*)(pWh + off) = hv;
            *(uint2*)(pWl + off) = lv;
        }
        __syncthreads();

        #pragma unroll
        for (int k16 = 0; k16 < 4; ++k16) {
            int k0 = k16 * 16;
            uint32_t ah[2][4], al[2][4];
            #pragma unroll
            for (int mf = 0; mf < 2; ++mf) {
                uint32_t off = SWZ((uint32_t)((wm * 32 + mf * 16 + aRow) * 128
                                              + (k0 + aK) * 2));
                ldsm4(ah[mf], sXh + off);
                ldsm4(al[mf], sXl + off);
            }
            #pragma unroll
            for (int nf2 = 0; nf2 < 8; ++nf2) {
                uint32_t offB = SWZ((uint32_t)((wn * 128 + nf2 * 16 + bRow) * 128
                                               + (k0 + bK) * 2));
                uint32_t bh[4], bl[4];
                ldsm4(bh, sWh + offB);
                ldsm4(bl, sWl + offB);
                #pragma unroll
                for (int mf = 0; mf < 2; ++mf) {
                    mma16816(acc[mf][2 * nf2],     ah[mf], bh);
                    mma16816(acc[mf][2 * nf2 + 1], ah[mf], bh + 2);
                    mma16816(acc[mf][2 * nf2],     ah[mf], bl);
                    mma16816(acc[mf][2 * nf2 + 1], ah[mf], bl + 2);
                    mma16816(acc[mf][2 * nf2],     al[mf], bh);
                    mma16816(acc[mf][2 * nf2 + 1], al[mf], bh + 2);
                }
            }
        }
    }

    // epilogue: write g_yr
    int grp = lane >> 2, qd = lane & 3;
    #pragma unroll
    for (int mf = 0; mf < 2; ++mf) {
        int r0 = m0 + wm * 32 + mf * 16 + grp;
        int r1 = r0 + 8;
        #pragma unroll
        for (int nf = 0; nf < 16; ++nf) {
            int col = wn * 128 + nf * 8 + qd * 2;
            if (r0 < N) {
                float2 v0 = make_float2(acc[mf][nf][0], acc[mf][nf][1]);
                *(float2*)(g_yr + (size_t)r0 * NTOT + col) = v0;
            }
            if (r1 < N) {
                float2 v1 = make_float2(acc[mf][nf][2], acc[mf][nf][3]);
                *(float2*)(g_yr + (size_t)r1 * NTOT + col) = v1;
            }
        }
    }
}

// ---------------------------------------------------------------- gather + epilogue
// one warp per dst node: mean-aggregate y, relu(z)*sh_w dot, out += (1-a)*score
__global__ void gather_kernel(const float* __restrict__ lin_l_b,
                              const float* __restrict__ sh_w,
                              const float* __restrict__ alpha,
                              float* __restrict__ out, int N) {
    int node = blockIdx.x * 8 + (threadIdx.x >> 5);
    int lane = threadIdx.x & 31;
    if (node >= N) return;
    float4 b4 = reinterpret_cast<const float4*>(lin_l_b)[lane];
    float4 s4 = reinterpret_cast<const float4*>(sh_w)[lane];
    int s0 = g_rowptr[node], s1 = g_rowptr[node + 1];
    float4 acc = make_float4(0.f, 0.f, 0.f, 0.f);
    int e = s0;
    for (; e + 1 < s1; e += 2) {
        int sa = g_srclist[e], sb = g_srclist[e + 1];
        float4 va = reinterpret_cast<const float4*>(g_yr + (size_t)sa * NTOT)[lane];
        float4 vb = reinterpret_cast<const float4*>(g_yr + (size_t)sb * NTOT)[lane];
        acc.x += va.x + vb.x; acc.y += va.y + vb.y;
        acc.z += va.z + vb.z; acc.w += va.w + vb.w;
    }
    if (e < s1) {
        int sa = g_srclist[e];
        float4 va = reinterpret_cast<const float4*>(g_yr + (size_t)sa * NTOT)[lane];
        acc.x += va.x; acc.y += va.y; acc.z += va.z; acc.w += va.w;
    }
    float inv = 1.f / fmaxf((float)(s1 - s0), 1.f);
    float4 r4 = reinterpret_cast<const float4*>(g_yr + (size_t)node * NTOT + HID)[lane];
    float part = fmaxf(acc.x * inv + b4.x + r4.x, 0.f) * s4.x
               + fmaxf(acc.y * inv + b4.y + r4.y, 0.f) * s4.y
               + fmaxf(acc.z * inv + b4.z + r4.z, 0.f) * s4.z
               + fmaxf(acc.w * inv + b4.w + r4.w, 0.f) * s4.w;
    #pragma unroll
    for (int o = 16; o; o >>= 1) part += __shfl_xor_sync(0xffffffffu, part, o);
    if (lane == 0) {
        float av = 1.f / (1.f + expf(-alpha[0]));
        out[node] += (1.f - av) * part;
    }
}

// ============================================================================
extern "C" void kernel_launch(void* const* d_in, const int* in_sizes, int n_in,
                              void* d_out, int out_size) {
    const float* x        = (const float*)d_in[0];
    const int*   ei       = (const int*)d_in[1];
    const float* rr       = (const float*)d_in[2];
    const float* lin_l_w  = (const float*)d_in[3];
    const float* lin_l_b  = (const float*)d_in[4];
    const float* lin_r_w  = (const float*)d_in[5];
    const float* rp_w     = (const float*)d_in[6];
    const float* rp_b     = (const float*)d_in[7];
    const float* sh_w     = (const float*)d_in[8];
    const float* sh_b     = (const float*)d_in[9];
    const float* alpha    = (const float*)d_in[10];
    float* out = (float*)d_out;

    int N = in_sizes[2];
    int E = in_sizes[1] / 2;
    if (E > MAXE) E = MAXE;
    int nblkN = (N + SCAN_B - 1) / SCAN_B;

    cudaFuncSetAttribute(mma_kernel,
                         cudaFuncAttributeMaxDynamicSharedMemorySize, 98304 + 256);

    detect_kernel<<<1, 32>>>((const unsigned*)ei);
    prep_kernel<<<1, 256>>>(rp_w, rp_b, sh_w, sh_b);
    base_kernel<<<(N + 7) / 8, 256>>>(x, rr, alpha, out, N);
    // CSR build
    zero_cnt_kernel<<<(N + 255) / 256, 256>>>(N);
    hist_kernel<<<(E + 255) / 256, 256>>>(ei, E, N);
    scanA_kernel<<<nblkN, SCAN_B>>>(N);
    scanB_kernel<<<1, SCAN_B>>>(nblkN);
    scanC_kernel<<<(N + 255) / 256, 256>>>(N, E);
    scatter_kernel<<<(E + 255) / 256, 256>>>(ei, E, N);
    // fused y|r GEMM on HMMA tensor cores
    mma_kernel<<<(N + 127) / 128, 256, 98304 + 256>>>(x, lin_l_w, lin_r_w, N);
    // mean-aggregate + relu + score + blend
    gather_kernel<<<(N + 7) / 8, 256>>>(lin_l_b, sh_w, alpha, out, N);
}

// round 10
// speedup vs baseline: 2.2843x; 1.0219x over previous
#include <cuda_runtime.h>
#include <cuda_bf16.h>
#include <math.h>
#include <stdint.h>

#define IN_DIM 256
#define HID    128
#define NTOT   256          // concat output cols: [y(128) | r(128)]
#define MAXN   100000
#define MAXE   600000
#define SCAN_B 1024

// ---- scratch (static device globals; no allocations allowed) ----
__device__ __align__(16) float g_yr[(size_t)MAXN * NTOT];   // [y | r] per node
__device__ __align__(16) float g_v[IN_DIM];                 // rp_w.T @ sh_w
__device__ float g_c0;
__device__ int   g_is64;
__device__ int g_cnt[MAXN];
__device__ int g_rowptr[MAXN + 1];
__device__ int g_cursor[MAXN];
__device__ int g_srclist[MAXE];
__device__ int g_bsum[(MAXN + SCAN_B - 1) / SCAN_B + 1];

// ---------------------------------------------------------------- helpers
__device__ __forceinline__ uint32_t smem_u32(const void* p) {
    uint32_t a;
    asm("{ .reg .u64 t; cvta.to.shared.u64 t, %1; cvt.u32.u64 %0, t; }"
        : "=r"(a) : "l"(p));
    return a;
}
__device__ __forceinline__ void ldsm4(uint32_t* r, uint32_t addr) {
    asm volatile("ldmatrix.sync.aligned.m8n8.x4.shared.b16 {%0,%1,%2,%3}, [%4];"
                 : "=r"(r[0]), "=r"(r[1]), "=r"(r[2]), "=r"(r[3]) : "r"(addr));
}
__device__ __forceinline__ void mma16816(float* c, const uint32_t* a,
                                         const uint32_t* b) {
    asm volatile("mma.sync.aligned.m16n8k16.row.col.f32.bf16.bf16.f32 "
                 "{%0,%1,%2,%3}, {%4,%5,%6,%7}, {%8,%9}, {%0,%1,%2,%3};"
                 : "+f"(c[0]), "+f"(c[1]), "+f"(c[2]), "+f"(c[3])
                 : "r"(a[0]), "r"(a[1]), "r"(a[2]), "r"(a[3]),
                   "r"(b[0]), "r"(b[1]));
}
#define SWZ(o) ((o) ^ (((o) >> 3) & 0x70))

__device__ __forceinline__ int load_idx(const int* ei, size_t pos) {
    if (g_is64) return (int)reinterpret_cast<const long long*>(ei)[pos];
    return ei[pos];
}

// ---------------------------------------------------------------- setup
// all blocks: zero g_cnt.  block 0 additionally: dtype detect + prep (v, c0).
__global__ void setup_kernel(const unsigned* __restrict__ ei32,
                             const float* __restrict__ rp_w,
                             const float* __restrict__ rp_b,
                             const float* __restrict__ sh_w,
                             const float* __restrict__ sh_b, int N) {
    int i = blockIdx.x * blockDim.x + threadIdx.x;
    if (i < N) g_cnt[i] = 0;
    if (blockIdx.x == 0) {
        int k = threadIdx.x;  // 256 threads
        // dtype detect (warp 0)
        if (k < 32) {
            int any = 0;
            for (int j = k; j < 64; j += 32)
                if (ei32[2 * j + 1] != 0u) any = 1;
            any = __any_sync(0xffffffffu, any);
            if (k == 0) g_is64 = !any;
        }
        // prep: v[k] = sum_h rp_w[h][k]*sh_w[h]
        float s = 0.f;
        for (int h = 0; h < HID; ++h) s += rp_w[h * IN_DIM + k] * sh_w[h];
        g_v[k] = s;
        if (k == 0) {
            float c = sh_b[0];
            for (int h = 0; h < HID; ++h) c += rp_b[h] * sh_w[h];
            g_c0 = c;
        }
    }
}

// ---------------------------------------------------------------- CSR build
__global__ void hist_kernel(const int* __restrict__ ei, int E, int N) {
    int e = blockIdx.x * blockDim.x + threadIdx.x;
    if (e >= E) return;
    int dst = load_idx(ei, (size_t)E + e);
    dst = min(max(dst, 0), N - 1);
    atomicAdd(&g_cnt[dst], 1);
}
__global__ void scanA_kernel(int N) {
    __shared__ int s[SCAN_B];
    int tid = threadIdx.x;
    int i = blockIdx.x * SCAN_B + tid;
    int v = (i < N) ? g_cnt[i] : 0;
    s[tid] = v;
    __syncthreads();
    for (int off = 1; off < SCAN_B; off <<= 1) {
        int t = (tid >= off) ? s[tid - off] : 0;
        __syncthreads();
        s[tid] += t;
        __syncthreads();
    }
    if (i < N) g_rowptr[i] = s[tid] - v;
    if (tid == SCAN_B - 1) g_bsum[blockIdx.x] = s[tid];
}
__global__ void scanB_kernel(int nb) {
    __shared__ int s[SCAN_B];
    int tid = threadIdx.x;
    int v = (tid < nb) ? g_bsum[tid] : 0;
    s[tid] = v;
    __syncthreads();
    for (int off = 1; off < SCAN_B; off <<= 1) {
        int t = (tid >= off) ? s[tid - off] : 0;
        __syncthreads();
        s[tid] += t;
        __syncthreads();
    }
    if (tid < nb) g_bsum[tid] = s[tid] - v;
}
__global__ void scanC_kernel(int N, int E) {
    int i = blockIdx.x * blockDim.x + threadIdx.x;
    if (i < N) {
        int r = g_rowptr[i] + g_bsum[i / SCAN_B];
        g_rowptr[i] = r;
        g_cursor[i] = r;
    }
    if (i == 0) g_rowptr[N] = E;
}
__global__ void scatter_kernel(const int* __restrict__ ei, int E, int N) {
    int e = blockIdx.x * blockDim.x + threadIdx.x;
    if (e >= E) return;
    int src = load_idx(ei, e);
    int dst = load_idx(ei, (size_t)E + e);
    src = min(max(src, 0), N - 1);
    dst = min(max(dst, 0), N - 1);
    int pos = atomicAdd(&g_cursor[dst], 1);
    if (pos < MAXE) g_srclist[pos] = src;
}

// ---------------------------------------------------------------- HMMA GEMM
// D[128 x 256] = X[128 x 256] @ [lin_l ; lin_r]^T  (bf16 split x3, fp32 acc)
// + fused residual-path base: out[node] = a*rr + (1-a)*(x.v + c0)
// 8 warps (4m x 2n), warp tile 32x128. K chunked at 64.
// smem: Xh 16K | Xl 16K | Wh 32K | Wl 32K | sDot 512B
__global__ __launch_bounds__(256, 1)
void mma_kernel(const float* __restrict__ x, const float* __restrict__ wl,
                const float* __restrict__ wr,
                const float* __restrict__ rr,
                const float* __restrict__ alpha,
                float* __restrict__ out, int N) {
    extern __shared__ char dsm[];
    uint32_t sb   = smem_u32(dsm);
    uint32_t base = (sb + 127) & ~127u;
    char*    db   = dsm + (base - sb);
    uint32_t sXh = base, sXl = base + 16384, sWh = base + 32768, sWl = base + 65536;
    char *pXh = db, *pXl = db + 16384, *pWh = db + 32768, *pWl = db + 65536;
    float* sDot = (float*)(db + 98304);

    int tid = threadIdx.x, wid = tid >> 5, lane = tid & 31;
    int wm = wid & 3, wn = wid >> 2;
    int m0 = blockIdx.x * 128;

    if (tid < 128) sDot[tid] = 0.f;
    __syncthreads();

    // ldmatrix lane address components
    int aRow = (lane & 7) + ((lane >> 3) & 1) * 8;
    int aK   = ((lane >> 4) & 1) * 8;
    int bRow = (lane & 7) + ((lane >> 4) & 1) * 8;
    int bK   = ((lane >> 3) & 1) * 8;

    float acc[2][16][4];
    #pragma unroll
    for (int i = 0; i < 2; ++i)
        #pragma unroll
        for (int j = 0; j < 16; ++j)
            #pragma unroll
            for (int q = 0; q < 4; ++q) acc[i][j][q] = 0.f;

    const int qf = tid & 15;           // chunk-invariant feature quad
    const int rbase = tid >> 4;        // row base (+ i*16 per iter)

    for (int c = 0; c < 4; ++c) {
        if (c) __syncthreads();   // previous chunk's MMA reads done
        float4 vv = *(const float4*)(g_v + c * 64 + qf * 4);
        // ---- X chunk: 128 rows x 64 feats -> bf16 hi/lo, SW128 (+ x.v dot)
        #pragma unroll
        for (int i = 0; i < 8; ++i) {
            int row = rbase + i * 16;
            int grow = min(m0 + row, N - 1);
            float4 f = *(const float4*)(x + (size_t)grow * IN_DIM + c * 64 + qf * 4);
            // residual dot partial: reduce across the 16 threads sharing `row`
            float dp = f.x * vv.x + f.y * vv.y + f.z * vv.z + f.w * vv.w;
            #pragma unroll
            for (int o = 1; o < 16; o <<= 1)
                dp += __shfl_xor_sync(0xffffffffu, dp, o);
            if (qf == 0) atomicAdd(&sDot[row], dp);
            __nv_bfloat16 h0 = __float2bfloat16_rn(f.x), h1 = __float2bfloat16_rn(f.y),
                          h2 = __float2bfloat16_rn(f.z), h3 = __float2bfloat16_rn(f.w);
            __nv_bfloat16 e0 = __float2bfloat16_rn(f.x - __bfloat162float(h0));
            __nv_bfloat16 e1 = __float2bfloat16_rn(f.y - __bfloat162float(h1));
            __nv_bfloat16 e2 = __float2bfloat16_rn(f.z - __bfloat162float(h2));
            __nv_bfloat16 e3 = __float2bfloat16_rn(f.w - __bfloat162float(h3));
            uint32_t off = SWZ((uint32_t)(row * 128 + qf * 8));
            uint2 hv, lv;
            hv.x = ((uint32_t)__bfloat16_as_ushort(h1) << 16) | __bfloat16_as_ushort(h0);
            hv.y = ((uint32_t)__bfloat16_as_ushort(h3) << 16) | __bfloat16_as_ushort(h2);
            lv.x = ((uint32_t)__bfloat16_as_ushort(e1) << 16) | __bfloat16_as_ushort(e0);
            lv.y = ((uint32_t)__bfloat16_as_ushort(e3) << 16) | __bfloat16_as_ushort(e2);
            *(uint2*)(pXh + off) = hv;
            *(uint2*)(pXl + off) = lv;
        }
        // ---- W chunk: 256 rows (lin_l then lin_r) x 64 feats
        #pragma unroll
        for (int i = 0; i < 16; ++i) {
            int l = tid + i * 256;
            int row = l >> 4;
            const float* srcp = (row < HID) ? (wl + (size_t)row * IN_DIM)
                                            : (wr + (size_t)(row - HID) * IN_DIM);
            float4 f = *(const float4*)(srcp + c * 64 + qf * 4);
            __nv_bfloat16 h0 = __float2bfloat16_rn(f.x), h1 = __float2bfloat16_rn(f.y),
                          h2 = __float2bfloat16_rn(f.z), h3 = __float2bfloat16_rn(f.w);
            __nv_bfloat16 e0 = __float2bfloat16_rn(f.x - __bfloat162float(h0));
            __nv_bfloat16 e1 = __float2bfloat16_rn(f.y - __bfloat162float(h1));
            __nv_bfloat16 e2 = __float2bfloat16_rn(f.z - __bfloat162float(h2));
            __nv_bfloat16 e3 = __float2bfloat16_rn(f.w - __bfloat162float(h3));
            uint32_t off = SWZ((uint32_t)(row * 128 + qf * 8));
            uint2 hv, lv;
            hv.x = ((uint32_t)__bfloat16_as_ushort(h1) << 16) | __bfloat16_as_ushort(h0);
            hv.y = ((uint32_t)__bfloat16_as_ushort(h3) << 16) | __bfloat16_as_ushort(h2);
            lv.x = ((uint32_t)__bfloat16_as_ushort(e1) << 16) | __bfloat16_as_ushort(e0);
            lv.y = ((uint32_t)__bfloat16_as_ushort(e3) << 16) | __bfloat16_as_ushort(e2);
            *(uint2*)(pWh + off) = hv;
            *(uint2*)(pWl + off) = lv;
        }
        __syncthreads();

        #pragma unroll
        for (int k16 = 0; k16 < 4; ++k16) {
            int k0 = k16 * 16;
            uint32_t ah[2][4], al[2][4];
            #pragma unroll
            for (int mf = 0; mf < 2; ++mf) {
                uint32_t off = SWZ((uint32_t)((wm * 32 + mf * 16 + aRow) * 128
                                              + (k0 + aK) * 2));
                ldsm4(ah[mf], sXh + off);
                ldsm4(al[mf], sXl + off);
            }
            #pragma unroll
            for (int nf2 = 0; nf2 < 8; ++nf2) {
                uint32_t offB = SWZ((uint32_t)((wn * 128 + nf2 * 16 + bRow) * 128
                                               + (k0 + bK) * 2));
                uint32_t bh[4], bl[4];
                ldsm4(bh, sWh + offB);
                ldsm4(bl, sWl + offB);
                #pragma unroll
                for (int mf = 0; mf < 2; ++mf) {
                    mma16816(acc[mf][2 * nf2],     ah[mf], bh);
                    mma16816(acc[mf][2 * nf2 + 1], ah[mf], bh + 2);
                    mma16816(acc[mf][2 * nf2],     ah[mf], bl);
                    mma16816(acc[mf][2 * nf2 + 1], ah[mf], bl + 2);
                    mma16816(acc[mf][2 * nf2],     al[mf], bh);
                    mma16816(acc[mf][2 * nf2 + 1], al[mf], bh + 2);
                }
            }
        }
    }

    // fused base epilogue: out[node] = a*rr + (1-a)*(x.v + c0)
    // (sDot complete: last chunk's atomics drained at the sync before its MMA)
    if (tid < 128) {
        int node = m0 + tid;
        if (node < N) {
            float av = 1.f / (1.f + expf(-alpha[0]));
            out[node] = av * rr[node] + (1.f - av) * (sDot[tid] + g_c0);
        }
    }

    // GEMM epilogue: write g_yr
    int grp = lane >> 2, qd = lane & 3;
    #pragma unroll
    for (int mf = 0; mf < 2; ++mf) {
        int r0 = m0 + wm * 32 + mf * 16 + grp;
        int r1 = r0 + 8;
        #pragma unroll
        for (int nf = 0; nf < 16; ++nf) {
            int col = wn * 128 + nf * 8 + qd * 2;
            if (r0 < N) {
                float2 v0 = make_float2(acc[mf][nf][0], acc[mf][nf][1]);
                *(float2*)(g_yr + (size_t)r0 * NTOT + col) = v0;
            }
            if (r1 < N) {
                float2 v1 = make_float2(acc[mf][nf][2], acc[mf][nf][3]);
                *(float2*)(g_yr + (size_t)r1 * NTOT + col) = v1;
            }
        }
    }
}

// ---------------------------------------------------------------- gather + epilogue
// one warp per dst node: mean-aggregate y, relu(z)*sh_w dot, out += (1-a)*score
__global__ void gather_kernel(const float* __restrict__ lin_l_b,
                              const float* __restrict__ sh_w,
                              const float* __restrict__ alpha,
                              float* __restrict__ out, int N) {
    int node = blockIdx.x * 8 + (threadIdx.x >> 5);
    int lane = threadIdx.x & 31;
    if (node >= N) return;
    float4 b4 = reinterpret_cast<const float4*>(lin_l_b)[lane];
    float4 s4 = reinterpret_cast<const float4*>(sh_w)[lane];
    int s0 = g_rowptr[node], s1 = g_rowptr[node + 1];
    float4 acc = make_float4(0.f, 0.f, 0.f, 0.f);
    int e = s0;
    for (; e + 1 < s1; e += 2) {
        int sa = g_srclist[e], sb = g_srclist[e + 1];
        float4 va = reinterpret_cast<const float4*>(g_yr + (size_t)sa * NTOT)[lane];
        float4 vb = reinterpret_cast<const float4*>(g_yr + (size_t)sb * NTOT)[lane];
        acc.x += va.x + vb.x; acc.y += va.y + vb.y;
        acc.z += va.z + vb.z; acc.w += va.w + vb.w;
    }
    if (e < s1) {
        int sa = g_srclist[e];
        float4 va = reinterpret_cast<const float4*>(g_yr + (size_t)sa * NTOT)[lane];
        acc.x += va.x; acc.y += va.y; acc.z += va.z; acc.w += va.w;
    }
    float inv = 1.f / fmaxf((float)(s1 - s0), 1.f);
    float4 r4 = reinterpret_cast<const float4*>(g_yr + (size_t)node * NTOT + HID)[lane];
    float part = fmaxf(acc.x * inv + b4.x + r4.x, 0.f) * s4.x
               + fmaxf(acc.y * inv + b4.y + r4.y, 0.f) * s4.y
               + fmaxf(acc.z * inv + b4.z + r4.z, 0.f) * s4.z
               + fmaxf(acc.w * inv + b4.w + r4.w, 0.f) * s4.w;
    #pragma unroll
    for (int o = 16; o; o >>= 1) part += __shfl_xor_sync(0xffffffffu, part, o);
    if (lane == 0) {
        float av = 1.f / (1.f + expf(-alpha[0]));
        out[node] += (1.f - av) * part;
    }
}

// ============================================================================
extern "C" void kernel_launch(void* const* d_in, const int* in_sizes, int n_in,
                              void* d_out, int out_size) {
    const float* x        = (const float*)d_in[0];
    const int*   ei       = (const int*)d_in[1];
    const float* rr       = (const float*)d_in[2];
    const float* lin_l_w  = (const float*)d_in[3];
    const float* lin_l_b  = (const float*)d_in[4];
    const float* lin_r_w  = (const float*)d_in[5];
    const float* rp_w     = (const float*)d_in[6];
    const float* rp_b     = (const float*)d_in[7];
    const float* sh_w     = (const float*)d_in[8];
    const float* sh_b     = (const float*)d_in[9];
    const float* alpha    = (const float*)d_in[10];
    float* out = (float*)d_out;

    int N = in_sizes[2];
    int E = in_sizes[1] / 2;
    if (E > MAXE) E = MAXE;
    int nblkN = (N + SCAN_B - 1) / SCAN_B;
    int smem = 98304 + 512 + 128;

    cudaFuncSetAttribute(mma_kernel,
                         cudaFuncAttributeMaxDynamicSharedMemorySize, smem);

    setup_kernel<<<(N + 255) / 256, 256>>>((const unsigned*)ei, rp_w, rp_b,
                                           sh_w, sh_b, N);
    hist_kernel<<<(E + 255) / 256, 256>>>(ei, E, N);
    scanA_kernel<<<nblkN, SCAN_B>>>(N);
    scanB_kernel<<<1, SCAN_B>>>(nblkN);
    scanC_kernel<<<(N + 255) / 256, 256>>>(N, E);
    scatter_kernel<<<(E + 255) / 256, 256>>>(ei, E, N);
    mma_kernel<<<(N + 127) / 128, 256, smem>>>(x, lin_l_w, lin_r_w,
                                               rr, alpha, out, N);
    gather_kernel<<<(N + 7) / 8, 256>>>(lin_l_b, sh_w, alpha, out, N);
}

// round 11
// speedup vs baseline: 2.5331x; 1.1089x over previous
#include <cuda_runtime.h>
#include <cuda_bf16.h>
#include <math.h>
#include <stdint.h>

#define IN_DIM 256
#define HID    128
#define NTOT   256          // concat output cols: [y(128) | r(128)]
#define MAXN   100000
#define MAXE   600000
#define SCAN_B 1024

// ---- scratch (static device globals; no allocations allowed) ----
__device__ __align__(16) float g_yr[(size_t)MAXN * NTOT];   // [y | r] per node
__device__ __align__(16) float g_v[IN_DIM];                 // rp_w.T @ sh_w
__device__ float g_c0;
__device__ int   g_is64;
__device__ int g_cnt[MAXN];
__device__ int g_rowptr[MAXN + 1];
__device__ int g_cursor[MAXN];
__device__ int g_srclist[MAXE];
__device__ int g_bsum[(MAXN + SCAN_B - 1) / SCAN_B + 1];
// pre-swizzled bf16 W smem images: per chunk c: [Wh 32KB | Wl 32KB]
__device__ __align__(16) char g_wimg[4 * 65536];

// ---------------------------------------------------------------- helpers
__device__ __forceinline__ uint32_t smem_u32(const void* p) {
    uint32_t a;
    asm("{ .reg .u64 t; cvta.to.shared.u64 t, %1; cvt.u32.u64 %0, t; }"
        : "=r"(a) : "l"(p));
    return a;
}
__device__ __forceinline__ void ldsm4(uint32_t* r, uint32_t addr) {
    asm volatile("ldmatrix.sync.aligned.m8n8.x4.shared.b16 {%0,%1,%2,%3}, [%4];"
                 : "=r"(r[0]), "=r"(r[1]), "=r"(r[2]), "=r"(r[3]) : "r"(addr));
}
__device__ __forceinline__ void mma16816(float* c, const uint32_t* a,
                                         const uint32_t* b) {
    asm volatile("mma.sync.aligned.m16n8k16.row.col.f32.bf16.bf16.f32 "
                 "{%0,%1,%2,%3}, {%4,%5,%6,%7}, {%8,%9}, {%0,%1,%2,%3};"
                 : "+f"(c[0]), "+f"(c[1]), "+f"(c[2]), "+f"(c[3])
                 : "r"(a[0]), "r"(a[1]), "r"(a[2]), "r"(a[3]),
                   "r"(b[0]), "r"(b[1]));
}
#define SWZ(o) ((o) ^ (((o) >> 3) & 0x70))

__device__ __forceinline__ int load_idx(const int* ei, size_t pos) {
    if (g_is64) return (int)reinterpret_cast<const long long*>(ei)[pos];
    return ei[pos];
}

__device__ __forceinline__ void cvt_hilo(float4 f, uint2& hv, uint2& lv) {
    __nv_bfloat16 h0 = __float2bfloat16_rn(f.x), h1 = __float2bfloat16_rn(f.y),
                  h2 = __float2bfloat16_rn(f.z), h3 = __float2bfloat16_rn(f.w);
    __nv_bfloat16 e0 = __float2bfloat16_rn(f.x - __bfloat162float(h0));
    __nv_bfloat16 e1 = __float2bfloat16_rn(f.y - __bfloat162float(h1));
    __nv_bfloat16 e2 = __float2bfloat16_rn(f.z - __bfloat162float(h2));
    __nv_bfloat16 e3 = __float2bfloat16_rn(f.w - __bfloat162float(h3));
    hv.x = ((uint32_t)__bfloat16_as_ushort(h1) << 16) | __bfloat16_as_ushort(h0);
    hv.y = ((uint32_t)__bfloat16_as_ushort(h3) << 16) | __bfloat16_as_ushort(h2);
    lv.x = ((uint32_t)__bfloat16_as_ushort(e1) << 16) | __bfloat16_as_ushort(e0);
    lv.y = ((uint32_t)__bfloat16_as_ushort(e3) << 16) | __bfloat16_as_ushort(e2);
}

// ---------------------------------------------------------------- setup
// all blocks: zero g_cnt.  block 0 additionally: dtype detect + prep (v, c0).
__global__ void setup_kernel(const unsigned* __restrict__ ei32,
                             const float* __restrict__ rp_w,
                             const float* __restrict__ rp_b,
                             const float* __restrict__ sh_w,
                             const float* __restrict__ sh_b, int N) {
    int i = blockIdx.x * blockDim.x + threadIdx.x;
    if (i < N) g_cnt[i] = 0;
    if (blockIdx.x == 0) {
        int k = threadIdx.x;  // 256 threads
        if (k < 32) {
            int any = 0;
            for (int j = k; j < 64; j += 32)
                if (ei32[2 * j + 1] != 0u) any = 1;
            any = __any_sync(0xffffffffu, any);
            if (k == 0) g_is64 = !any;
        }
        float s = 0.f;
        for (int h = 0; h < HID; ++h) s += rp_w[h * IN_DIM + k] * sh_w[h];
        g_v[k] = s;
        if (k == 0) {
            float c = sh_b[0];
            for (int h = 0; h < HID; ++h) c += rp_b[h] * sh_w[h];
            g_c0 = c;
        }
    }
}

// ---------------------------------------------------------------- W image
// 16384 threads: chunk c = t>>12, row = (t&4095)>>4, qf = t&15
__global__ void wconv_kernel(const float* __restrict__ wl,
                             const float* __restrict__ wr) {
    int t = blockIdx.x * blockDim.x + threadIdx.x;
    int c = t >> 12, l = t & 4095;
    int row = l >> 4, qf = l & 15;
    const float* srcp = (row < HID) ? (wl + (size_t)row * IN_DIM)
                                    : (wr + (size_t)(row - HID) * IN_DIM);
    float4 f = *(const float4*)(srcp + c * 64 + qf * 4);
    uint2 hv, lv;
    cvt_hilo(f, hv, lv);
    uint32_t off = SWZ((uint32_t)(row * 128 + qf * 8));
    *(uint2*)(g_wimg + c * 65536 + off) = hv;
    *(uint2*)(g_wimg + c * 65536 + 32768 + off) = lv;
}

// ---------------------------------------------------------------- CSR build
__global__ void hist_kernel(const int* __restrict__ ei, int E, int N) {
    int e = blockIdx.x * blockDim.x + threadIdx.x;
    if (e >= E) return;
    int dst = load_idx(ei, (size_t)E + e);
    dst = min(max(dst, 0), N - 1);
    atomicAdd(&g_cnt[dst], 1);
}
__global__ void scanA_kernel(int N) {
    __shared__ int s[SCAN_B];
    int tid = threadIdx.x;
    int i = blockIdx.x * SCAN_B + tid;
    int v = (i < N) ? g_cnt[i] : 0;
    s[tid] = v;
    __syncthreads();
    for (int off = 1; off < SCAN_B; off <<= 1) {
        int t = (tid >= off) ? s[tid - off] : 0;
        __syncthreads();
        s[tid] += t;
        __syncthreads();
    }
    if (i < N) g_rowptr[i] = s[tid] - v;
    if (tid == SCAN_B - 1) g_bsum[blockIdx.x] = s[tid];
}
__global__ void scanB_kernel(int nb) {
    __shared__ int s[SCAN_B];
    int tid = threadIdx.x;
    int v = (tid < nb) ? g_bsum[tid] : 0;
    s[tid] = v;
    __syncthreads();
    for (int off = 1; off < SCAN_B; off <<= 1) {
        int t = (tid >= off) ? s[tid - off] : 0;
        __syncthreads();
        s[tid] += t;
        __syncthreads();
    }
    if (tid < nb) g_bsum[tid] = s[tid] - v;
}
__global__ void scanC_kernel(int N, int E) {
    int i = blockIdx.x * blockDim.x + threadIdx.x;
    if (i < N) {
        int r = g_rowptr[i] + g_bsum[i / SCAN_B];
        g_rowptr[i] = r;
        g_cursor[i] = r;
    }
    if (i == 0) g_rowptr[N] = E;
}
__global__ void scatter_kernel(const int* __restrict__ ei, int E, int N) {
    int e = blockIdx.x * blockDim.x + threadIdx.x;
    if (e >= E) return;
    int src = load_idx(ei, e);
    int dst = load_idx(ei, (size_t)E + e);
    src = min(max(src, 0), N - 1);
    dst = min(max(dst, 0), N - 1);
    int pos = atomicAdd(&g_cursor[dst], 1);
    if (pos < MAXE) g_srclist[pos] = src;
}

// ---------------------------------------------------------------- HMMA GEMM
// D[128 x 256] = X[128 x 256] @ [lin_l ; lin_r]^T  (bf16 split x3, fp32 acc)
// + fused residual-path base: out[node] = a*rr + (1-a)*(x.v + c0)
// W comes pre-converted/pre-swizzled from g_wimg (16 uint4 copies per chunk).
__global__ __launch_bounds__(256, 1)
void mma_kernel(const float* __restrict__ x,
                const float* __restrict__ rr,
                const float* __restrict__ alpha,
                float* __restrict__ out, int N) {
    extern __shared__ char dsm[];
    uint32_t sb   = smem_u32(dsm);
    uint32_t base = (sb + 127) & ~127u;
    char*    db   = dsm + (base - sb);
    uint32_t sXh = base, sXl = base + 16384, sWh = base + 32768, sWl = base + 65536;
    char *pXh = db, *pXl = db + 16384, *pWh = db + 32768;
    float* sDot = (float*)(db + 98304);

    int tid = threadIdx.x, wid = tid >> 5, lane = tid & 31;
    int wm = wid & 3, wn = wid >> 2;
    int m0 = blockIdx.x * 128;

    if (tid < 128) sDot[tid] = 0.f;
    __syncthreads();

    int aRow = (lane & 7) + ((lane >> 3) & 1) * 8;
    int aK   = ((lane >> 4) & 1) * 8;
    int bRow = (lane & 7) + ((lane >> 4) & 1) * 8;
    int bK   = ((lane >> 3) & 1) * 8;

    float acc[2][16][4];
    #pragma unroll
    for (int i = 0; i < 2; ++i)
        #pragma unroll
        for (int j = 0; j < 16; ++j)
            #pragma unroll
            for (int q = 0; q < 4; ++q) acc[i][j][q] = 0.f;

    const int qf = tid & 15;
    const int rbase = tid >> 4;

    for (int c = 0; c < 4; ++c) {
        if (c) __syncthreads();
        float4 vv = *(const float4*)(g_v + c * 64 + qf * 4);
        // ---- X chunk: 128 rows x 64 feats -> bf16 hi/lo, SW128 (+ x.v dot)
        #pragma unroll
        for (int i = 0; i < 8; ++i) {
            int row = rbase + i * 16;
            int grow = min(m0 + row, N - 1);
            float4 f = *(const float4*)(x + (size_t)grow * IN_DIM + c * 64 + qf * 4);
            float dp = f.x * vv.x + f.y * vv.y + f.z * vv.z + f.w * vv.w;
            #pragma unroll
            for (int o = 1; o < 16; o <<= 1)
                dp += __shfl_xor_sync(0xffffffffu, dp, o);
            if (qf == 0) atomicAdd(&sDot[row], dp);
            uint2 hv, lv;
            cvt_hilo(f, hv, lv);
            uint32_t off = SWZ((uint32_t)(row * 128 + qf * 8));
            *(uint2*)(pXh + off) = hv;
            *(uint2*)(pXl + off) = lv;
        }
        // ---- W chunk: straight copy of pre-swizzled image (Wh|Wl = 64KB)
        {
            const uint4* wsrc = (const uint4*)(g_wimg + c * 65536);
            uint4* wdst = (uint4*)pWh;
            #pragma unroll
            for (int i = 0; i < 16; ++i) {
                int t = tid + i * 256;
                wdst[t] = wsrc[t];
            }
        }
        __syncthreads();

        #pragma unroll
        for (int k16 = 0; k16 < 4; ++k16) {
            int k0 = k16 * 16;
            uint32_t ah[2][4], al[2][4];
            #pragma unroll
            for (int mf = 0; mf < 2; ++mf) {
                uint32_t off = SWZ((uint32_t)((wm * 32 + mf * 16 + aRow) * 128
                                              + (k0 + aK) * 2));
                ldsm4(ah[mf], sXh + off);
                ldsm4(al[mf], sXl + off);
            }
            #pragma unroll
            for (int nf2 = 0; nf2 < 8; ++nf2) {
                uint32_t offB = SWZ((uint32_t)((wn * 128 + nf2 * 16 + bRow) * 128
                                               + (k0 + bK) * 2));
                uint32_t bh[4], bl[4];
                ldsm4(bh, sWh + offB);
                ldsm4(bl, sWl + offB);
                #pragma unroll
                for (int mf = 0; mf < 2; ++mf) {
                    mma16816(acc[mf][2 * nf2],     ah[mf], bh);
                    mma16816(acc[mf][2 * nf2 + 1], ah[mf], bh + 2);
                    mma16816(acc[mf][2 * nf2],     ah[mf], bl);
                    mma16816(acc[mf][2 * nf2 + 1], ah[mf], bl + 2);
                    mma16816(acc[mf][2 * nf2],     al[mf], bh);
                    mma16816(acc[mf][2 * nf2 + 1], al[mf], bh + 2);
                }
            }
        }
    }

    // fused base epilogue: out[node] = a*rr + (1-a)*(x.v + c0)
    if (tid < 128) {
        int node = m0 + tid;
        if (node < N) {
            float av = 1.f / (1.f + expf(-alpha[0]));
            out[node] = av * rr[node] + (1.f - av) * (sDot[tid] + g_c0);
        }
    }

    // GEMM epilogue: write g_yr
    int grp = lane >> 2, qd = lane & 3;
    #pragma unroll
    for (int mf = 0; mf < 2; ++mf) {
        int r0 = m0 + wm * 32 + mf * 16 + grp;
        int r1 = r0 + 8;
        #pragma unroll
        for (int nf = 0; nf < 16; ++nf) {
            int col = wn * 128 + nf * 8 + qd * 2;
            if (r0 < N) {
                float2 v0 = make_float2(acc[mf][nf][0], acc[mf][nf][1]);
                *(float2*)(g_yr + (size_t)r0 * NTOT + col) = v0;
            }
            if (r1 < N) {
                float2 v1 = make_float2(acc[mf][nf][2], acc[mf][nf][3]);
                *(float2*)(g_yr + (size_t)r1 * NTOT + col) = v1;
            }
        }
    }
}

// ---------------------------------------------------------------- gather + epilogue
__global__ void gather_kernel(const float* __restrict__ lin_l_b,
                              const float* __restrict__ sh_w,
                              const float* __restrict__ alpha,
                              float* __restrict__ out, int N) {
    int node = blockIdx.x * 8 + (threadIdx.x >> 5);
    int lane = threadIdx.x & 31;
    if (node >= N) return;
    float4 b4 = reinterpret_cast<const float4*>(lin_l_b)[lane];
    float4 s4 = reinterpret_cast<const float4*>(sh_w)[lane];
    int s0 = g_rowptr[node], s1 = g_rowptr[node + 1];
    float4 acc = make_float4(0.f, 0.f, 0.f, 0.f);
    int e = s0;
    for (; e + 1 < s1; e += 2) {
        int sa = g_srclist[e], sb = g_srclist[e + 1];
        float4 va = reinterpret_cast<const float4*>(g_yr + (size_t)sa * NTOT)[lane];
        float4 vb = reinterpret_cast<const float4*>(g_yr + (size_t)sb * NTOT)[lane];
        acc.x += va.x + vb.x; acc.y += va.y + vb.y;
        acc.z += va.z + vb.z; acc.w += va.w + vb.w;
    }
    if (e < s1) {
        int sa = g_srclist[e];
        float4 va = reinterpret_cast<const float4*>(g_yr + (size_t)sa * NTOT)[lane];
        acc.x += va.x; acc.y += va.y; acc.z += va.z; acc.w += va.w;
    }
    float inv = 1.f / fmaxf((float)(s1 - s0), 1.f);
    float4 r4 = reinterpret_cast<const float4*>(g_yr + (size_t)node * NTOT + HID)[lane];
    float part = fmaxf(acc.x * inv + b4.x + r4.x, 0.f) * s4.x
               + fmaxf(acc.y * inv + b4.y + r4.y, 0.f) * s4.y
               + fmaxf(acc.z * inv + b4.z + r4.z, 0.f) * s4.z
               + fmaxf(acc.w * inv + b4.w + r4.w, 0.f) * s4.w;
    #pragma unroll
    for (int o = 16; o; o >>= 1) part += __shfl_xor_sync(0xffffffffu, part, o);
    if (lane == 0) {
        float av = 1.f / (1.f + expf(-alpha[0]));
        out[node] += (1.f - av) * part;
    }
}

// ============================================================================
extern "C" void kernel_launch(void* const* d_in, const int* in_sizes, int n_in,
                              void* d_out, int out_size) {
    const float* x        = (const float*)d_in[0];
    const int*   ei       = (const int*)d_in[1];
    const float* rr       = (const float*)d_in[2];
    const float* lin_l_w  = (const float*)d_in[3];
    const float* lin_l_b  = (const float*)d_in[4];
    const float* lin_r_w  = (const float*)d_in[5];
    const float* rp_w     = (const float*)d_in[6];
    const float* rp_b     = (const float*)d_in[7];
    const float* sh_w     = (const float*)d_in[8];
    const float* sh_b     = (const float*)d_in[9];
    const float* alpha    = (const float*)d_in[10];
    float* out = (float*)d_out;

    int N = in_sizes[2];
    int E = in_sizes[1] / 2;
    if (E > MAXE) E = MAXE;
    int nblkN = (N + SCAN_B - 1) / SCAN_B;
    int smem = 98304 + 512 + 128;

    cudaFuncSetAttribute(mma_kernel,
                         cudaFuncAttributeMaxDynamicSharedMemorySize, smem);

    // fork a side stream for the CSR build (capture-safe via event edges).
    // Host objects only; created during capture, not replayed. Not destroyed
    // mid-capture (destroying a stream inside an active capture invalidates it).
    cudaStream_t s2;
    cudaStreamCreateWithFlags(&s2, cudaStreamNonBlocking);
    cudaEvent_t evRoot, evSetup, evCSR;
    cudaEventCreateWithFlags(&evRoot, cudaEventDisableTiming);
    cudaEventCreateWithFlags(&evSetup, cudaEventDisableTiming);
    cudaEventCreateWithFlags(&evCSR, cudaEventDisableTiming);

    cudaEventRecord(evRoot, 0);
    cudaStreamWaitEvent(s2, evRoot, 0);

    // side stream: setup + CSR build
    setup_kernel<<<(N + 255) / 256, 256, 0, s2>>>((const unsigned*)ei, rp_w,
                                                  rp_b, sh_w, sh_b, N);
    cudaEventRecord(evSetup, s2);
    hist_kernel<<<(E + 255) / 256, 256, 0, s2>>>(ei, E, N);
    scanA_kernel<<<nblkN, SCAN_B, 0, s2>>>(N);
    scanB_kernel<<<1, SCAN_B, 0, s2>>>(nblkN);
    scanC_kernel<<<(N + 255) / 256, 256, 0, s2>>>(N, E);
    scatter_kernel<<<(E + 255) / 256, 256, 0, s2>>>(ei, E, N);
    cudaEventRecord(evCSR, s2);

    // main stream: W image, then GEMM (needs g_v/g_c0 from setup)
    wconv_kernel<<<64, 256>>>(lin_l_w, lin_r_w);
    cudaStreamWaitEvent(0, evSetup, 0);
    mma_kernel<<<(N + 127) / 128, 256, smem>>>(x, rr, alpha, out, N);
    cudaStreamWaitEvent(0, evCSR, 0);
    gather_kernel<<<(N + 7) / 8, 256>>>(lin_l_b, sh_w, alpha, out, N);
}

// round 12
// speedup vs baseline: 2.6877x; 1.0611x over previous
#include <cuda_runtime.h>
#include <cuda_bf16.h>
#include <math.h>
#include <stdint.h>

#define IN_DIM 256
#define HID    128
#define NTOT   256          // concat output cols: [y(128) | r(128)]
#define MAXN   100000
#define MAXE   600000
#define SCAN_B 1024

// ---- scratch (static device globals; no allocations allowed) ----
__device__ __align__(16) float g_yr[(size_t)MAXN * NTOT];   // [y | r] per node
__device__ __align__(16) float g_v[IN_DIM];                 // rp_w.T @ sh_w
__device__ float g_c0;
__device__ int   g_is64;
__device__ int g_cnt[MAXN];
__device__ int g_rowptr[MAXN + 1];
__device__ int g_cursor[MAXN];
__device__ int g_srclist[MAXE];
__device__ int g_bsum[(MAXN + SCAN_B - 1) / SCAN_B + 1];
// pre-swizzled bf16 W smem images: per chunk c: [Wh 32KB | Wl 32KB]
__device__ __align__(16) char g_wimg[4 * 65536];

// ---------------------------------------------------------------- helpers
__device__ __forceinline__ uint32_t smem_u32(const void* p) {
    uint32_t a;
    asm("{ .reg .u64 t; cvta.to.shared.u64 t, %1; cvt.u32.u64 %0, t; }"
        : "=r"(a) : "l"(p));
    return a;
}
__device__ __forceinline__ void ldsm4(uint32_t* r, uint32_t addr) {
    asm volatile("ldmatrix.sync.aligned.m8n8.x4.shared.b16 {%0,%1,%2,%3}, [%4];"
                 : "=r"(r[0]), "=r"(r[1]), "=r"(r[2]), "=r"(r[3]) : "r"(addr));
}
__device__ __forceinline__ void mma16816(float* c, const uint32_t* a,
                                         const uint32_t* b) {
    asm volatile("mma.sync.aligned.m16n8k16.row.col.f32.bf16.bf16.f32 "
                 "{%0,%1,%2,%3}, {%4,%5,%6,%7}, {%8,%9}, {%0,%1,%2,%3};"
                 : "+f"(c[0]), "+f"(c[1]), "+f"(c[2]), "+f"(c[3])
                 : "r"(a[0]), "r"(a[1]), "r"(a[2]), "r"(a[3]),
                   "r"(b[0]), "r"(b[1]));
}
__device__ __forceinline__ void cpa16(uint32_t dst, const void* src) {
    asm volatile("cp.async.cg.shared.global [%0], [%1], 16;"
                 :: "r"(dst), "l"(src) : "memory");
}
__device__ __forceinline__ void cpa_commit() {
    asm volatile("cp.async.commit_group;" ::: "memory");
}
__device__ __forceinline__ void cpa_wait1() {
    asm volatile("cp.async.wait_group 1;" ::: "memory");
}
__device__ __forceinline__ void cpa_wait0() {
    asm volatile("cp.async.wait_group 0;" ::: "memory");
}
#define SWZ(o) ((o) ^ (((o) >> 3) & 0x70))

__device__ __forceinline__ int load_idx(const int* ei, size_t pos) {
    if (g_is64) return (int)reinterpret_cast<const long long*>(ei)[pos];
    return ei[pos];
}

__device__ __forceinline__ void cvt_hilo(float4 f, uint2& hv, uint2& lv) {
    __nv_bfloat16 h0 = __float2bfloat16_rn(f.x), h1 = __float2bfloat16_rn(f.y),
                  h2 = __float2bfloat16_rn(f.z), h3 = __float2bfloat16_rn(f.w);
    __nv_bfloat16 e0 = __float2bfloat16_rn(f.x - __bfloat162float(h0));
    __nv_bfloat16 e1 = __float2bfloat16_rn(f.y - __bfloat162float(h1));
    __nv_bfloat16 e2 = __float2bfloat16_rn(f.z - __bfloat162float(h2));
    __nv_bfloat16 e3 = __float2bfloat16_rn(f.w - __bfloat162float(h3));
    hv.x = ((uint32_t)__bfloat16_as_ushort(h1) << 16) | __bfloat16_as_ushort(h0);
    hv.y = ((uint32_t)__bfloat16_as_ushort(h3) << 16) | __bfloat16_as_ushort(h2);
    lv.x = ((uint32_t)__bfloat16_as_ushort(e1) << 16) | __bfloat16_as_ushort(e0);
    lv.y = ((uint32_t)__bfloat16_as_ushort(e3) << 16) | __bfloat16_as_ushort(e2);
}

// ---------------------------------------------------------------- setup
__global__ void setup_kernel(const unsigned* __restrict__ ei32,
                             const float* __restrict__ rp_w,
                             const float* __restrict__ rp_b,
                             const float* __restrict__ sh_w,
                             const float* __restrict__ sh_b, int N) {
    int i = blockIdx.x * blockDim.x + threadIdx.x;
    if (i < N) g_cnt[i] = 0;
    if (blockIdx.x == 0) {
        int k = threadIdx.x;  // 256 threads
        if (k < 32) {
            int any = 0;
            for (int j = k; j < 64; j += 32)
                if (ei32[2 * j + 1] != 0u) any = 1;
            any = __any_sync(0xffffffffu, any);
            if (k == 0) g_is64 = !any;
        }
        float s = 0.f;
        for (int h = 0; h < HID; ++h) s += rp_w[h * IN_DIM + k] * sh_w[h];
        g_v[k] = s;
        if (k == 0) {
            float c = sh_b[0];
            for (int h = 0; h < HID; ++h) c += rp_b[h] * sh_w[h];
            g_c0 = c;
        }
    }
}

// ---------------------------------------------------------------- W image
__global__ void wconv_kernel(const float* __restrict__ wl,
                             const float* __restrict__ wr) {
    int t = blockIdx.x * blockDim.x + threadIdx.x;
    int c = t >> 12, l = t & 4095;
    int row = l >> 4, qf = l & 15;
    const float* srcp = (row < HID) ? (wl + (size_t)row * IN_DIM)
                                    : (wr + (size_t)(row - HID) * IN_DIM);
    float4 f = *(const float4*)(srcp + c * 64 + qf * 4);
    uint2 hv, lv;
    cvt_hilo(f, hv, lv);
    uint32_t off = SWZ((uint32_t)(row * 128 + qf * 8));
    *(uint2*)(g_wimg + c * 65536 + off) = hv;
    *(uint2*)(g_wimg + c * 65536 + 32768 + off) = lv;
}

// ---------------------------------------------------------------- CSR build
__global__ void hist_kernel(const int* __restrict__ ei, int E, int N) {
    int e = blockIdx.x * blockDim.x + threadIdx.x;
    if (e >= E) return;
    int dst = load_idx(ei, (size_t)E + e);
    dst = min(max(dst, 0), N - 1);
    atomicAdd(&g_cnt[dst], 1);
}
__global__ void scanA_kernel(int N) {
    __shared__ int s[SCAN_B];
    int tid = threadIdx.x;
    int i = blockIdx.x * SCAN_B + tid;
    int v = (i < N) ? g_cnt[i] : 0;
    s[tid] = v;
    __syncthreads();
    for (int off = 1; off < SCAN_B; off <<= 1) {
        int t = (tid >= off) ? s[tid - off] : 0;
        __syncthreads();
        s[tid] += t;
        __syncthreads();
    }
    if (i < N) g_rowptr[i] = s[tid] - v;
    if (tid == SCAN_B - 1) g_bsum[blockIdx.x] = s[tid];
}
__global__ void scanB_kernel(int nb) {
    __shared__ int s[SCAN_B];
    int tid = threadIdx.x;
    int v = (tid < nb) ? g_bsum[tid] : 0;
    s[tid] = v;
    __syncthreads();
    for (int off = 1; off < SCAN_B; off <<= 1) {
        int t = (tid >= off) ? s[tid - off] : 0;
        __syncthreads();
        s[tid] += t;
        __syncthreads();
    }
    if (tid < nb) g_bsum[tid] = s[tid] - v;
}
__global__ void scanC_kernel(int N, int E) {
    int i = blockIdx.x * blockDim.x + threadIdx.x;
    if (i < N) {
        int r = g_rowptr[i] + g_bsum[i / SCAN_B];
        g_rowptr[i] = r;
        g_cursor[i] = r;
    }
    if (i == 0) g_rowptr[N] = E;
}
__global__ void scatter_kernel(const int* __restrict__ ei, int E, int N) {
    int e = blockIdx.x * blockDim.x + threadIdx.x;
    if (e >= E) return;
    int src = load_idx(ei, e);
    int dst = load_idx(ei, (size_t)E + e);
    src = min(max(src, 0), N - 1);
    dst = min(max(dst, 0), N - 1);
    int pos = atomicAdd(&g_cursor[dst], 1);
    if (pos < MAXE) g_srclist[pos] = src;
}

// ---------------------------------------------------------------- HMMA GEMM
// D[128 x 256] = X[128 x 256] @ [lin_l ; lin_r]^T  (bf16 split x3, fp32 acc)
// + fused base epilogue.  W via double-buffered cp.async from g_wimg.
// smem: Xh 16K | Xl 16K | Wbuf0 64K | Wbuf1 64K | sDot
__global__ __launch_bounds__(256, 1)
void mma_kernel(const float* __restrict__ x,
                const float* __restrict__ rr,
                const float* __restrict__ alpha,
                float* __restrict__ out, int N) {
    extern __shared__ char dsm[];
    uint32_t sb   = smem_u32(dsm);
    uint32_t base = (sb + 127) & ~127u;
    char*    db   = dsm + (base - sb);
    uint32_t sXh = base, sXl = base + 16384;
    uint32_t sW  = base + 32768;           // two 64KB buffers
    char *pXh = db, *pXl = db + 16384;
    float* sDot = (float*)(db + 163840);

    int tid = threadIdx.x, wid = tid >> 5, lane = tid & 31;
    int wm = wid & 3, wn = wid >> 2;
    int m0 = blockIdx.x * 128;

    if (tid < 128) sDot[tid] = 0.f;

    int aRow = (lane & 7) + ((lane >> 3) & 1) * 8;
    int aK   = ((lane >> 4) & 1) * 8;
    int bRow = (lane & 7) + ((lane >> 4) & 1) * 8;
    int bK   = ((lane >> 3) & 1) * 8;

    float acc[2][16][4];
    #pragma unroll
    for (int i = 0; i < 2; ++i)
        #pragma unroll
        for (int j = 0; j < 16; ++j)
            #pragma unroll
            for (int q = 0; q < 4; ++q) acc[i][j][q] = 0.f;

    const int qf = tid & 15;
    const int rbase = tid >> 4;

    // prologue: async-fetch W chunk 0 into buffer 0
    {
        const char* wsrc = g_wimg;
        #pragma unroll
        for (int i = 0; i < 16; ++i) {
            int t = (tid + i * 256) * 16;
            cpa16(sW + t, wsrc + t);
        }
        cpa_commit();
    }
    __syncthreads();   // sDot zero visible

    for (int c = 0; c < 4; ++c) {
        if (c) __syncthreads();   // prev MMA done reading sX + W buf (c-1)&1
        float4 vv = *(const float4*)(g_v + c * 64 + qf * 4);
        // ---- X chunk: 128 rows x 64 feats -> bf16 hi/lo, SW128 (+ x.v dot)
        #pragma unroll
        for (int i = 0; i < 8; ++i) {
            int row = rbase + i * 16;
            int grow = min(m0 + row, N - 1);
            float4 f = *(const float4*)(x + (size_t)grow * IN_DIM + c * 64 + qf * 4);
            float dp = f.x * vv.x + f.y * vv.y + f.z * vv.z + f.w * vv.w;
            #pragma unroll
            for (int o = 1; o < 16; o <<= 1)
                dp += __shfl_xor_sync(0xffffffffu, dp, o);
            if (qf == 0) atomicAdd(&sDot[row], dp);
            uint2 hv, lv;
            cvt_hilo(f, hv, lv);
            uint32_t off = SWZ((uint32_t)(row * 128 + qf * 8));
            *(uint2*)(pXh + off) = hv;
            *(uint2*)(pXl + off) = lv;
        }
        // ---- issue next W chunk into the buffer freed by chunk c-1
        if (c < 3) {
            const char* wsrc = g_wimg + (c + 1) * 65536;
            uint32_t wdst = sW + ((c + 1) & 1) * 65536;
            #pragma unroll
            for (int i = 0; i < 16; ++i) {
                int t = (tid + i * 256) * 16;
                cpa16(wdst + t, wsrc + t);
            }
            cpa_commit();
            cpa_wait1();   // chunk c's group complete
        } else {
            cpa_wait0();
        }
        __syncthreads();

        uint32_t sWh = sW + (c & 1) * 65536;
        uint32_t sWl = sWh + 32768;
        #pragma unroll
        for (int k16 = 0; k16 < 4; ++k16) {
            int k0 = k16 * 16;
            uint32_t ah[2][4], al[2][4];
            #pragma unroll
            for (int mf = 0; mf < 2; ++mf) {
                uint32_t off = SWZ((uint32_t)((wm * 32 + mf * 16 + aRow) * 128
                                              + (k0 + aK) * 2));
                ldsm4(ah[mf], sXh + off);
                ldsm4(al[mf], sXl + off);
            }
            #pragma unroll
            for (int nf2 = 0; nf2 < 8; ++nf2) {
                uint32_t offB = SWZ((uint32_t)((wn * 128 + nf2 * 16 + bRow) * 128
                                               + (k0 + bK) * 2));
                uint32_t bh[4], bl[4];
                ldsm4(bh, sWh + offB);
                ldsm4(bl, sWl + offB);
                #pragma unroll
                for (int mf = 0; mf < 2; ++mf) {
                    mma16816(acc[mf][2 * nf2],     ah[mf], bh);
                    mma16816(acc[mf][2 * nf2 + 1], ah[mf], bh + 2);
                    mma16816(acc[mf][2 * nf2],     ah[mf], bl);
                    mma16816(acc[mf][2 * nf2 + 1], ah[mf], bl + 2);
                    mma16816(acc[mf][2 * nf2],     al[mf], bh);
                    mma16816(acc[mf][2 * nf2 + 1], al[mf], bh + 2);
                }
            }
        }
    }

    // fused base epilogue: out[node] = a*rr + (1-a)*(x.v + c0)
    if (tid < 128) {
        int node = m0 + tid;
        if (node < N) {
            float av = 1.f / (1.f + expf(-alpha[0]));
            out[node] = av * rr[node] + (1.f - av) * (sDot[tid] + g_c0);
        }
    }

    // GEMM epilogue: write g_yr
    int grp = lane >> 2, qd = lane & 3;
    #pragma unroll
    for (int mf = 0; mf < 2; ++mf) {
        int r0 = m0 + wm * 32 + mf * 16 + grp;
        int r1 = r0 + 8;
        #pragma unroll
        for (int nf = 0; nf < 16; ++nf) {
            int col = wn * 128 + nf * 8 + qd * 2;
            if (r0 < N) {
                float2 v0 = make_float2(acc[mf][nf][0], acc[mf][nf][1]);
                *(float2*)(g_yr + (size_t)r0 * NTOT + col) = v0;
            }
            if (r1 < N) {
                float2 v1 = make_float2(acc[mf][nf][2], acc[mf][nf][3]);
                *(float2*)(g_yr + (size_t)r1 * NTOT + col) = v1;
            }
        }
    }
}

// ---------------------------------------------------------------- gather + epilogue
__global__ void gather_kernel(const float* __restrict__ lin_l_b,
                              const float* __restrict__ sh_w,
                              const float* __restrict__ alpha,
                              float* __restrict__ out, int N) {
    int node = blockIdx.x * 8 + (threadIdx.x >> 5);
    int lane = threadIdx.x & 31;
    if (node >= N) return;
    float4 b4 = reinterpret_cast<const float4*>(lin_l_b)[lane];
    float4 s4 = reinterpret_cast<const float4*>(sh_w)[lane];
    int s0 = g_rowptr[node], s1 = g_rowptr[node + 1];
    float4 acc = make_float4(0.f, 0.f, 0.f, 0.f);
    int e = s0;
    for (; e + 1 < s1; e += 2) {
        int sa = g_srclist[e], sb = g_srclist[e + 1];
        float4 va = reinterpret_cast<const float4*>(g_yr + (size_t)sa * NTOT)[lane];
        float4 vb = reinterpret_cast<const float4*>(g_yr + (size_t)sb * NTOT)[lane];
        acc.x += va.x + vb.x; acc.y += va.y + vb.y;
        acc.z += va.z + vb.z; acc.w += va.w + vb.w;
    }
    if (e < s1) {
        int sa = g_srclist[e];
        float4 va = reinterpret_cast<const float4*>(g_yr + (size_t)sa * NTOT)[lane];
        acc.x += va.x; acc.y += va.y; acc.z += va.z; acc.w += va.w;
    }
    float inv = 1.f / fmaxf((float)(s1 - s0), 1.f);
    float4 r4 = reinterpret_cast<const float4*>(g_yr + (size_t)node * NTOT + HID)[lane];
    float part = fmaxf(acc.x * inv + b4.x + r4.x, 0.f) * s4.x
               + fmaxf(acc.y * inv + b4.y + r4.y, 0.f) * s4.y
               + fmaxf(acc.z * inv + b4.z + r4.z, 0.f) * s4.z
               + fmaxf(acc.w * inv + b4.w + r4.w, 0.f) * s4.w;
    #pragma unroll
    for (int o = 16; o; o >>= 1) part += __shfl_xor_sync(0xffffffffu, part, o);
    if (lane == 0) {
        float av = 1.f / (1.f + expf(-alpha[0]));
        out[node] += (1.f - av) * part;
    }
}

// ============================================================================
extern "C" void kernel_launch(void* const* d_in, const int* in_sizes, int n_in,
                              void* d_out, int out_size) {
    const float* x        = (const float*)d_in[0];
    const int*   ei       = (const int*)d_in[1];
    const float* rr       = (const float*)d_in[2];
    const float* lin_l_w  = (const float*)d_in[3];
    const float* lin_l_b  = (const float*)d_in[4];
    const float* lin_r_w  = (const float*)d_in[5];
    const float* rp_w     = (const float*)d_in[6];
    const float* rp_b     = (const float*)d_in[7];
    const float* sh_w     = (const float*)d_in[8];
    const float* sh_b     = (const float*)d_in[9];
    const float* alpha    = (const float*)d_in[10];
    float* out = (float*)d_out;

    int N = in_sizes[2];
    int E = in_sizes[1] / 2;
    if (E > MAXE) E = MAXE;
    int nblkN = (N + SCAN_B - 1) / SCAN_B;
    int smem = 163840 + 512 + 128;

    cudaFuncSetAttribute(mma_kernel,
                         cudaFuncAttributeMaxDynamicSharedMemorySize, smem);

    // fork a side stream for the CSR build (capture-safe via event edges)
    cudaStream_t s2;
    cudaStreamCreateWithFlags(&s2, cudaStreamNonBlocking);
    cudaEvent_t evRoot, evSetup, evCSR;
    cudaEventCreateWithFlags(&evRoot, cudaEventDisableTiming);
    cudaEventCreateWithFlags(&evSetup, cudaEventDisableTiming);
    cudaEventCreateWithFlags(&evCSR, cudaEventDisableTiming);

    cudaEventRecord(evRoot, 0);
    cudaStreamWaitEvent(s2, evRoot, 0);

    // side stream: setup + CSR build
    setup_kernel<<<(N + 255) / 256, 256, 0, s2>>>((const unsigned*)ei, rp_w,
                                                  rp_b, sh_w, sh_b, N);
    cudaEventRecord(evSetup, s2);
    hist_kernel<<<(E + 255) / 256, 256, 0, s2>>>(ei, E, N);
    scanA_kernel<<<nblkN, SCAN_B, 0, s2>>>(N);
    scanB_kernel<<<1, SCAN_B, 0, s2>>>(nblkN);
    scanC_kernel<<<(N + 255) / 256, 256, 0, s2>>>(N, E);
    scatter_kernel<<<(E + 255) / 256, 256, 0, s2>>>(ei, E, N);
    cudaEventRecord(evCSR, s2);

    // main stream: W image, then GEMM (needs g_v/g_c0 from setup)
    wconv_kernel<<<64, 256>>>(lin_l_w, lin_r_w);
    cudaStreamWaitEvent(0, evSetup, 0);
    mma_kernel<<<(N + 127) / 128, 256, smem>>>(x, rr, alpha, out, N);
    cudaStreamWaitEvent(0, evCSR, 0);
    gather_kernel<<<(N + 7) / 8, 256>>>(lin_l_b, sh_w, alpha, out, N);
}

// round 13
// speedup vs baseline: 3.1384x; 1.1677x over previous
#include <cuda_runtime.h>
#include <cuda_bf16.h>
#include <math.h>
#include <stdint.h>

#define IN_DIM 256
#define HID    128
#define NTOT   256          // concat output cols: [y(128) | r(128)]
#define MAXN   100000
#define MAXE   600000
#define SCAN_B 1024

// ---- scratch (static device globals; no allocations allowed) ----
__device__ __align__(16) float g_yr[(size_t)MAXN * NTOT];   // [y | r] per node
__device__ __align__(16) float g_v[IN_DIM];                 // rp_w.T @ sh_w
__device__ float g_c0;
__device__ int   g_is64;
__device__ int g_cnt[MAXN];
__device__ int g_rowptr[MAXN + 1];
__device__ int g_cursor[MAXN];
__device__ int g_srclist[MAXE];
__device__ int g_bsum[(MAXN + SCAN_B - 1) / SCAN_B + 1];
// pre-swizzled bf16 W smem images: per chunk c: [Wh 32KB | Wl 32KB]
__device__ __align__(16) char g_wimg[4 * 65536];

// ---------------------------------------------------------------- helpers
__device__ __forceinline__ uint32_t smem_u32(const void* p) {
    uint32_t a;
    asm("{ .reg .u64 t; cvta.to.shared.u64 t, %1; cvt.u32.u64 %0, t; }"
        : "=r"(a) : "l"(p));
    return a;
}
__device__ __forceinline__ void ldsm4(uint32_t* r, uint32_t addr) {
    asm volatile("ldmatrix.sync.aligned.m8n8.x4.shared.b16 {%0,%1,%2,%3}, [%4];"
                 : "=r"(r[0]), "=r"(r[1]), "=r"(r[2]), "=r"(r[3]) : "r"(addr));
}
__device__ __forceinline__ void mma16816(float* c, const uint32_t* a,
                                         const uint32_t* b) {
    asm volatile("mma.sync.aligned.m16n8k16.row.col.f32.bf16.bf16.f32 "
                 "{%0,%1,%2,%3}, {%4,%5,%6,%7}, {%8,%9}, {%0,%1,%2,%3};"
                 : "+f"(c[0]), "+f"(c[1]), "+f"(c[2]), "+f"(c[3])
                 : "r"(a[0]), "r"(a[1]), "r"(a[2]), "r"(a[3]),
                   "r"(b[0]), "r"(b[1]));
}
__device__ __forceinline__ void cpa16(uint32_t dst, const void* src) {
    asm volatile("cp.async.cg.shared.global [%0], [%1], 16;"
                 :: "r"(dst), "l"(src) : "memory");
}
__device__ __forceinline__ void cpa_commit() {
    asm volatile("cp.async.commit_group;" ::: "memory");
}
__device__ __forceinline__ void cpa_wait1() {
    asm volatile("cp.async.wait_group 1;" ::: "memory");
}
__device__ __forceinline__ void cpa_wait0() {
    asm volatile("cp.async.wait_group 0;" ::: "memory");
}
#define SWZ(o) ((o) ^ (((o) >> 3) & 0x70))

__device__ __forceinline__ int load_idx(const int* ei, size_t pos) {
    if (g_is64) return (int)reinterpret_cast<const long long*>(ei)[pos];
    return ei[pos];
}

// rn-based split (used for W image; slightly better W precision)
__device__ __forceinline__ void cvt_hilo(float4 f, uint2& hv, uint2& lv) {
    __nv_bfloat16 h0 = __float2bfloat16_rn(f.x), h1 = __float2bfloat16_rn(f.y),
                  h2 = __float2bfloat16_rn(f.z), h3 = __float2bfloat16_rn(f.w);
    __nv_bfloat16 e0 = __float2bfloat16_rn(f.x - __bfloat162float(h0));
    __nv_bfloat16 e1 = __float2bfloat16_rn(f.y - __bfloat162float(h1));
    __nv_bfloat16 e2 = __float2bfloat16_rn(f.z - __bfloat162float(h2));
    __nv_bfloat16 e3 = __float2bfloat16_rn(f.w - __bfloat162float(h3));
    hv.x = ((uint32_t)__bfloat16_as_ushort(h1) << 16) | __bfloat16_as_ushort(h0);
    hv.y = ((uint32_t)__bfloat16_as_ushort(h3) << 16) | __bfloat16_as_ushort(h2);
    lv.x = ((uint32_t)__bfloat16_as_ushort(e1) << 16) | __bfloat16_as_ushort(e0);
    lv.y = ((uint32_t)__bfloat16_as_ushort(e3) << 16) | __bfloat16_as_ushort(e2);
}

// trunc-based split (X path; PRMT pack, hi=trunc16(f), lo=rn(f-hi))
__device__ __forceinline__ void cvt_trunc(float4 f, uint2& hv, uint2& lv) {
    uint32_t u0 = __float_as_uint(f.x), u1 = __float_as_uint(f.y);
    uint32_t u2 = __float_as_uint(f.z), u3 = __float_as_uint(f.w);
    hv.x = __byte_perm(u0, u1, 0x7632);
    hv.y = __byte_perm(u2, u3, 0x7632);
    float e0 = f.x - __uint_as_float(u0 & 0xFFFF0000u);
    float e1 = f.y - __uint_as_float(u1 & 0xFFFF0000u);
    float e2 = f.z - __uint_as_float(u2 & 0xFFFF0000u);
    float e3 = f.w - __uint_as_float(u3 & 0xFFFF0000u);
    asm("cvt.rn.bf16x2.f32 %0, %1, %2;" : "=r"(lv.x) : "f"(e1), "f"(e0));
    asm("cvt.rn.bf16x2.f32 %0, %1, %2;" : "=r"(lv.y) : "f"(e3), "f"(e2));
}

// ---------------------------------------------------------------- setup
__global__ void setup_kernel(const unsigned* __restrict__ ei32,
                             const float* __restrict__ rp_w,
                             const float* __restrict__ rp_b,
                             const float* __restrict__ sh_w,
                             const float* __restrict__ sh_b, int N) {
    int i = blockIdx.x * blockDim.x + threadIdx.x;
    if (i < N) g_cnt[i] = 0;
    if (blockIdx.x == 0) {
        int k = threadIdx.x;  // 256 threads
        if (k < 32) {
            int any = 0;
            for (int j = k; j < 64; j += 32)
                if (ei32[2 * j + 1] != 0u) any = 1;
            any = __any_sync(0xffffffffu, any);
            if (k == 0) g_is64 = !any;
        }
        float s = 0.f;
        for (int h = 0; h < HID; ++h) s += rp_w[h * IN_DIM + k] * sh_w[h];
        g_v[k] = s;
        if (k == 0) {
            float c = sh_b[0];
            for (int h = 0; h < HID; ++h) c += rp_b[h] * sh_w[h];
            g_c0 = c;
        }
    }
}

// ---------------------------------------------------------------- W image
__global__ void wconv_kernel(const float* __restrict__ wl,
                             const float* __restrict__ wr) {
    int t = blockIdx.x * blockDim.x + threadIdx.x;
    int c = t >> 12, l = t & 4095;
    int row = l >> 4, qf = l & 15;
    const float* srcp = (row < HID) ? (wl + (size_t)row * IN_DIM)
                                    : (wr + (size_t)(row - HID) * IN_DIM);
    float4 f = *(const float4*)(srcp + c * 64 + qf * 4);
    uint2 hv, lv;
    cvt_hilo(f, hv, lv);
    uint32_t off = SWZ((uint32_t)(row * 128 + qf * 8));
    *(uint2*)(g_wimg + c * 65536 + off) = hv;
    *(uint2*)(g_wimg + c * 65536 + 32768 + off) = lv;
}

// ---------------------------------------------------------------- CSR build
__global__ void hist_kernel(const int* __restrict__ ei, int E, int N) {
    int e = blockIdx.x * blockDim.x + threadIdx.x;
    if (e >= E) return;
    int dst = load_idx(ei, (size_t)E + e);
    dst = min(max(dst, 0), N - 1);
    atomicAdd(&g_cnt[dst], 1);
}
__global__ void scanA_kernel(int N) {
    __shared__ int s[SCAN_B];
    int tid = threadIdx.x;
    int i = blockIdx.x * SCAN_B + tid;
    int v = (i < N) ? g_cnt[i] : 0;
    s[tid] = v;
    __syncthreads();
    for (int off = 1; off < SCAN_B; off <<= 1) {
        int t = (tid >= off) ? s[tid - off] : 0;
        __syncthreads();
        s[tid] += t;
        __syncthreads();
    }
    if (i < N) g_rowptr[i] = s[tid] - v;
    if (tid == SCAN_B - 1) g_bsum[blockIdx.x] = s[tid];
}
__global__ void scanB_kernel(int nb) {
    __shared__ int s[SCAN_B];
    int tid = threadIdx.x;
    int v = (tid < nb) ? g_bsum[tid] : 0;
    s[tid] = v;
    __syncthreads();
    for (int off = 1; off < SCAN_B; off <<= 1) {
        int t = (tid >= off) ? s[tid - off] : 0;
        __syncthreads();
        s[tid] += t;
        __syncthreads();
    }
    if (tid < nb) g_bsum[tid] = s[tid] - v;
}
__global__ void scanC_kernel(int N, int E) {
    int i = blockIdx.x * blockDim.x + threadIdx.x;
    if (i < N) {
        int r = g_rowptr[i] + g_bsum[i / SCAN_B];
        g_rowptr[i] = r;
        g_cursor[i] = r;
    }
    if (i == 0) g_rowptr[N] = E;
}
__global__ void scatter_kernel(const int* __restrict__ ei, int E, int N) {
    int e = blockIdx.x * blockDim.x + threadIdx.x;
    if (e >= E) return;
    int src = load_idx(ei, e);
    int dst = load_idx(ei, (size_t)E + e);
    src = min(max(src, 0), N - 1);
    dst = min(max(dst, 0), N - 1);
    int pos = atomicAdd(&g_cursor[dst], 1);
    if (pos < MAXE) g_srclist[pos] = src;
}

// ---------------------------------------------------------------- HMMA GEMM
// D[128 x 256] = X[128 x 256] @ [lin_l ; lin_r]^T  (bf16 split x3, fp32 acc)
// X register-pipelined; W double-buffered cp.async; base epilogue via dp[8].
// smem: Xh 16K | Xl 16K | Wbuf0 64K | Wbuf1 64K
__global__ __launch_bounds__(256, 1)
void mma_kernel(const float* __restrict__ x,
                const float* __restrict__ rr,
                const float* __restrict__ alpha,
                float* __restrict__ out, int N) {
    extern __shared__ char dsm[];
    uint32_t sb   = smem_u32(dsm);
    uint32_t base = (sb + 127) & ~127u;
    char*    db   = dsm + (base - sb);
    uint32_t sXh = base, sXl = base + 16384;
    uint32_t sW  = base + 32768;           // two 64KB buffers
    char *pXh = db, *pXl = db + 16384;

    int tid = threadIdx.x, wid = tid >> 5, lane = tid & 31;
    int wm = wid & 3, wn = wid >> 2;
    int m0 = blockIdx.x * 128;

    int aRow = (lane & 7) + ((lane >> 3) & 1) * 8;
    int aK   = ((lane >> 4) & 1) * 8;
    int bRow = (lane & 7) + ((lane >> 4) & 1) * 8;
    int bK   = ((lane >> 3) & 1) * 8;

    float acc[2][16][4];
    #pragma unroll
    for (int i = 0; i < 2; ++i)
        #pragma unroll
        for (int j = 0; j < 16; ++j)
            #pragma unroll
            for (int q = 0; q < 4; ++q) acc[i][j][q] = 0.f;

    const int qf = tid & 15;
    const int rbase = tid >> 4;
    float dp[8];
    #pragma unroll
    for (int i = 0; i < 8; ++i) dp[i] = 0.f;

    // prologue: async-fetch W chunk 0; preload X chunk 0 into registers
    {
        const char* wsrc = g_wimg;
        #pragma unroll
        for (int i = 0; i < 16; ++i) {
            int t = (tid + i * 256) * 16;
            cpa16(sW + t, wsrc + t);
        }
        cpa_commit();
    }
    float4 px[8];
    #pragma unroll
    for (int i = 0; i < 8; ++i) {
        int grow = min(m0 + rbase + 16 * i, N - 1);
        px[i] = *(const float4*)(x + (size_t)grow * IN_DIM + qf * 4);
    }

    for (int c = 0; c < 4; ++c) {
        if (c) __syncthreads();   // prev MMA done reading sX + W buf (c-1)&1
        float4 vv = *(const float4*)(g_v + c * 64 + qf * 4);
        // ---- convert preloaded X chunk -> smem; accumulate dot partials
        #pragma unroll
        for (int i = 0; i < 8; ++i) {
            int row = rbase + i * 16;
            float4 f = px[i];
            dp[i] += f.x * vv.x + f.y * vv.y + f.z * vv.z + f.w * vv.w;
            uint2 hv, lv;
            cvt_trunc(f, hv, lv);
            uint32_t off = SWZ((uint32_t)(row * 128 + qf * 8));
            *(uint2*)(pXh + off) = hv;
            *(uint2*)(pXl + off) = lv;
        }
        // ---- preload next X chunk (completes during MMA)
        if (c < 3) {
            #pragma unroll
            for (int i = 0; i < 8; ++i) {
                int grow = min(m0 + rbase + 16 * i, N - 1);
                px[i] = *(const float4*)(x + (size_t)grow * IN_DIM
                                         + (c + 1) * 64 + qf * 4);
            }
        }
        // ---- issue next W chunk into the buffer freed by chunk c-1
        if (c < 3) {
            const char* wsrc = g_wimg + (c + 1) * 65536;
            uint32_t wdst = sW + ((c + 1) & 1) * 65536;
            #pragma unroll
            for (int i = 0; i < 16; ++i) {
                int t = (tid + i * 256) * 16;
                cpa16(wdst + t, wsrc + t);
            }
            cpa_commit();
            cpa_wait1();   // chunk c's group complete
        } else {
            cpa_wait0();
        }
        __syncthreads();

        uint32_t sWh = sW + (c & 1) * 65536;
        uint32_t sWl = sWh + 32768;
        #pragma unroll
        for (int k16 = 0; k16 < 4; ++k16) {
            int k0 = k16 * 16;
            uint32_t ah[2][4], al[2][4];
            #pragma unroll
            for (int mf = 0; mf < 2; ++mf) {
                uint32_t off = SWZ((uint32_t)((wm * 32 + mf * 16 + aRow) * 128
                                              + (k0 + aK) * 2));
                ldsm4(ah[mf], sXh + off);
                ldsm4(al[mf], sXl + off);
            }
            #pragma unroll
            for (int nf2 = 0; nf2 < 8; ++nf2) {
                uint32_t offB = SWZ((uint32_t)((wn * 128 + nf2 * 16 + bRow) * 128
                                               + (k0 + bK) * 2));
                uint32_t bh[4], bl[4];
                ldsm4(bh, sWh + offB);
                ldsm4(bl, sWl + offB);
                #pragma unroll
                for (int mf = 0; mf < 2; ++mf) {
                    mma16816(acc[mf][2 * nf2],     ah[mf], bh);
                    mma16816(acc[mf][2 * nf2 + 1], ah[mf], bh + 2);
                    mma16816(acc[mf][2 * nf2],     ah[mf], bl);
                    mma16816(acc[mf][2 * nf2 + 1], ah[mf], bl + 2);
                    mma16816(acc[mf][2 * nf2],     al[mf], bh);
                    mma16816(acc[mf][2 * nf2 + 1], al[mf], bh + 2);
                }
            }
        }
    }

    // fused base epilogue: one reduce per row, single-writer store
    {
        float av = 1.f / (1.f + expf(-alpha[0]));
        #pragma unroll
        for (int i = 0; i < 8; ++i) {
            float d = dp[i];
            #pragma unroll
            for (int o = 1; o < 16; o <<= 1)
                d += __shfl_xor_sync(0xffffffffu, d, o);
            if (qf == 0) {
                int node = m0 + rbase + 16 * i;
                if (node < N)
                    out[node] = av * rr[node] + (1.f - av) * (d + g_c0);
            }
        }
    }

    // GEMM epilogue: write g_yr
    int grp = lane >> 2, qd = lane & 3;
    #pragma unroll
    for (int mf = 0; mf < 2; ++mf) {
        int r0 = m0 + wm * 32 + mf * 16 + grp;
        int r1 = r0 + 8;
        #pragma unroll
        for (int nf = 0; nf < 16; ++nf) {
            int col = wn * 128 + nf * 8 + qd * 2;
            if (r0 < N) {
                float2 v0 = make_float2(acc[mf][nf][0], acc[mf][nf][1]);
                *(float2*)(g_yr + (size_t)r0 * NTOT + col) = v0;
            }
            if (r1 < N) {
                float2 v1 = make_float2(acc[mf][nf][2], acc[mf][nf][3]);
                *(float2*)(g_yr + (size_t)r1 * NTOT + col) = v1;
            }
        }
    }
}

// ---------------------------------------------------------------- gather + epilogue
__global__ void gather_kernel(const float* __restrict__ lin_l_b,
                              const float* __restrict__ sh_w,
                              const float* __restrict__ alpha,
                              float* __restrict__ out, int N) {
    int node = blockIdx.x * 8 + (threadIdx.x >> 5);
    int lane = threadIdx.x & 31;
    if (node >= N) return;
    float4 b4 = reinterpret_cast<const float4*>(lin_l_b)[lane];
    float4 s4 = reinterpret_cast<const float4*>(sh_w)[lane];
    int s0 = g_rowptr[node], s1 = g_rowptr[node + 1];
    float4 acc = make_float4(0.f, 0.f, 0.f, 0.f);
    int e = s0;
    for (; e + 1 < s1; e += 2) {
        int sa = g_srclist[e], sb = g_srclist[e + 1];
        float4 va = reinterpret_cast<const float4*>(g_yr + (size_t)sa * NTOT)[lane];
        float4 vb = reinterpret_cast<const float4*>(g_yr + (size_t)sb * NTOT)[lane];
        acc.x += va.x + vb.x; acc.y += va.y + vb.y;
        acc.z += va.z + vb.z; acc.w += va.w + vb.w;
    }
    if (e < s1) {
        int sa = g_srclist[e];
        float4 va = reinterpret_cast<const float4*>(g_yr + (size_t)sa * NTOT)[lane];
        acc.x += va.x; acc.y += va.y; acc.z += va.z; acc.w += va.w;
    }
    float inv = 1.f / fmaxf((float)(s1 - s0), 1.f);
    float4 r4 = reinterpret_cast<const float4*>(g_yr + (size_t)node * NTOT + HID)[lane];
    float part = fmaxf(acc.x * inv + b4.x + r4.x, 0.f) * s4.x
               + fmaxf(acc.y * inv + b4.y + r4.y, 0.f) * s4.y
               + fmaxf(acc.z * inv + b4.z + r4.z, 0.f) * s4.z
               + fmaxf(acc.w * inv + b4.w + r4.w, 0.f) * s4.w;
    #pragma unroll
    for (int o = 16; o; o >>= 1) part += __shfl_xor_sync(0xffffffffu, part, o);
    if (lane == 0) {
        float av = 1.f / (1.f + expf(-alpha[0]));
        out[node] += (1.f - av) * part;
    }
}

// ============================================================================
extern "C" void kernel_launch(void* const* d_in, const int* in_sizes, int n_in,
                              void* d_out, int out_size) {
    const float* x        = (const float*)d_in[0];
    const int*   ei       = (const int*)d_in[1];
    const float* rr       = (const float*)d_in[2];
    const float* lin_l_w  = (const float*)d_in[3];
    const float* lin_l_b  = (const float*)d_in[4];
    const float* lin_r_w  = (const float*)d_in[5];
    const float* rp_w     = (const float*)d_in[6];
    const float* rp_b     = (const float*)d_in[7];
    const float* sh_w     = (const float*)d_in[8];
    const float* sh_b     = (const float*)d_in[9];
    const float* alpha    = (const float*)d_in[10];
    float* out = (float*)d_out;

    int N = in_sizes[2];
    int E = in_sizes[1] / 2;
    if (E > MAXE) E = MAXE;
    int nblkN = (N + SCAN_B - 1) / SCAN_B;
    int smem = 163840 + 128;

    cudaFuncSetAttribute(mma_kernel,
                         cudaFuncAttributeMaxDynamicSharedMemorySize, smem);

    // fork a side stream for the CSR build (capture-safe via event edges)
    cudaStream_t s2;
    cudaStreamCreateWithFlags(&s2, cudaStreamNonBlocking);
    cudaEvent_t evRoot, evSetup, evCSR;
    cudaEventCreateWithFlags(&evRoot, cudaEventDisableTiming);
    cudaEventCreateWithFlags(&evSetup, cudaEventDisableTiming);
    cudaEventCreateWithFlags(&evCSR, cudaEventDisableTiming);

    cudaEventRecord(evRoot, 0);
    cudaStreamWaitEvent(s2, evRoot, 0);

    // side stream: setup + CSR build
    setup_kernel<<<(N + 255) / 256, 256, 0, s2>>>((const unsigned*)ei, rp_w,
                                                  rp_b, sh_w, sh_b, N);
    cudaEventRecord(evSetup, s2);
    hist_kernel<<<(E + 255) / 256, 256, 0, s2>>>(ei, E, N);
    scanA_kernel<<<nblkN, SCAN_B, 0, s2>>>(N);
    scanB_kernel<<<1, SCAN_B, 0, s2>>>(nblkN);
    scanC_kernel<<<(N + 255) / 256, 256, 0, s2>>>(N, E);
    scatter_kernel<<<(E + 255) / 256, 256, 0, s2>>>(ei, E, N);
    cudaEventRecord(evCSR, s2);

    // main stream: W image, then GEMM (needs g_v/g_c0 from setup)
    wconv_kernel<<<64, 256>>>(lin_l_w, lin_r_w);
    cudaStreamWaitEvent(0, evSetup, 0);
    mma_kernel<<<(N + 127) / 128, 256, smem>>>(x, rr, alpha, out, N);
    cudaStreamWaitEvent(0, evCSR, 0);
    gather_kernel<<<(N + 7) / 8, 256>>>(lin_l_b, sh_w, alpha, out, N);
}